// round 1
// baseline (speedup 1.0000x reference)
#include <cuda_runtime.h>
#include <math.h>

#define NB 30
#define NODES 135
#define NROWS (NB*NODES)     // 4050
#define NPAIRS 9045

#define BN_S 0.9999950001f   // 1/sqrt(1+1e-5)
#define RRELU_S 0.2291666667f

// ---- scratch (static device globals; no allocation) ----
__device__ float g_s1[NROWS*16*186];   // after stage1: (4050,16,186)
__device__ float g_s2[NROWS*32*92];    // after stage2: (4050,32,92)
__device__ float g_s3[NROWS*48*45];    // after stage3: (4050,48,45) == (4050,2160)
__device__ float g_feats[NROWS*32];    // (4050,32)
__device__ float g_subj[NB*NPAIRS];    // (30,9045)
__device__ float g_part[8*NB*1024];    // split-K partials
__device__ float g_c1[NB*1024];
__device__ float g_c2[NB*256];
__device__ float g_c3[NB*64];

__device__ __forceinline__ float leaky(float v){ return v > 0.f ? v : 0.01f*v; }

// ============================================================
// K1: conv1(1->32,k3) + BN + leaky + pool(2x2 over C,L) -> (4050,16,186)
// one thread per (row, pooled-l), computes all 16 pooled channels
// ============================================================
__global__ void k1(const float* __restrict__ x, const float* __restrict__ w,
                   const float* __restrict__ cb, const float* __restrict__ g,
                   const float* __restrict__ bb) {
    __shared__ float ws[96], As[32], Bs[32];
    int tid = threadIdx.x;
    if (tid < 96) ws[tid] = w[tid];
    if (tid < 32) { float a = g[tid]*BN_S; As[tid]=a; Bs[tid]=fmaf(cb[tid],a,bb[tid]); }
    __syncthreads();
    int idx = blockIdx.x*blockDim.x + tid;
    if (idx >= NROWS*186) return;
    int n = idx / 186, l = idx % 186;
    const float* xp = x + n*375 + 2*l;
    float x0=xp[0], x1=xp[1], x2=xp[2], x3=xp[3];
    #pragma unroll
    for (int c=0;c<16;c++){
        int c0=2*c, c1=2*c+1;
        float wa0=ws[c0*3],wa1=ws[c0*3+1],wa2=ws[c0*3+2];
        float wb0=ws[c1*3],wb1=ws[c1*3+1],wb2=ws[c1*3+2];
        float p00 = x0*wa0 + x1*wa1 + x2*wa2;
        float p01 = x1*wa0 + x2*wa1 + x3*wa2;
        float p10 = x0*wb0 + x1*wb1 + x2*wb2;
        float p11 = x1*wb0 + x2*wb1 + x3*wb2;
        float a0=As[c0],b0=Bs[c0],a1=As[c1],b1=Bs[c1];
        float v = fmaxf(fmaxf(leaky(fmaf(p00,a0,b0)), leaky(fmaf(p01,a0,b0))),
                        fmaxf(leaky(fmaf(p10,a1,b1)), leaky(fmaf(p11,a1,b1))));
        g_s1[(n*16+c)*186 + l] = v;
    }
}

// ============================================================
// K2: conv2(16->64,k3)+BN+leaky+pool -> (4050,32,92). block per row.
// ============================================================
__global__ void k2(const float* __restrict__ w, const float* __restrict__ cb,
                   const float* __restrict__ g, const float* __restrict__ bb){
    __shared__ float xs[16*186];      // 2976
    __shared__ float ws[64*16*3];     // 3072
    __shared__ float As[64], Bs[64];
    int n = blockIdx.x, tid = threadIdx.x;
    for (int i=tid;i<16*186;i+=256) xs[i] = g_s1[n*(16*186)+i];
    for (int i=tid;i<3072;i+=256)   ws[i] = w[i];
    if (tid<64){ float a=g[tid]*BN_S; As[tid]=a; Bs[tid]=fmaf(cb[tid],a,bb[tid]); }
    __syncthreads();
    for (int t=tid;t<736;t+=256){       // 32 c-tiles x 23 l-tiles (4 pooled l each)
        int c = t & 31, lt = t >> 5;
        int l0 = lt*4, px = 2*l0;
        float acc0[8]={0,0,0,0,0,0,0,0}, acc1[8]={0,0,0,0,0,0,0,0};
        for (int ci=0; ci<16; ci++){
            const float* xp = xs + ci*186 + px;
            float xv[10];
            #pragma unroll
            for (int q=0;q<10;q++) xv[q]=xp[q];
            const float* wp = ws + (2*c*16+ci)*3;
            const float* wq = ws + ((2*c+1)*16+ci)*3;
            float wa0=wp[0],wa1=wp[1],wa2=wp[2];
            float wb0=wq[0],wb1=wq[1],wb2=wq[2];
            #pragma unroll
            for (int p=0;p<8;p++){
                acc0[p] = fmaf(xv[p],wa0,fmaf(xv[p+1],wa1,fmaf(xv[p+2],wa2,acc0[p])));
                acc1[p] = fmaf(xv[p],wb0,fmaf(xv[p+1],wb1,fmaf(xv[p+2],wb2,acc1[p])));
            }
        }
        float a0=As[2*c],b0=Bs[2*c],a1=As[2*c+1],b1=Bs[2*c+1];
        #pragma unroll
        for (int q=0;q<4;q++){
            float v = fmaxf(fmaxf(leaky(fmaf(acc0[2*q],a0,b0)), leaky(fmaf(acc0[2*q+1],a0,b0))),
                            fmaxf(leaky(fmaf(acc1[2*q],a1,b1)), leaky(fmaf(acc1[2*q+1],a1,b1))));
            g_s2[(n*32+c)*92 + l0+q] = v;
        }
    }
}

// ============================================================
// K3: conv3(32->96,k3)+BN+leaky+pool -> (4050,48,45). block per row.
// (BN params read from gmem in epilogue to keep static smem <= 48KB)
// ============================================================
__global__ void k3(const float* __restrict__ w, const float* __restrict__ cb,
                   const float* __restrict__ g, const float* __restrict__ bb){
    __shared__ float xs[32*92];       // 2944
    __shared__ float ws[96*32*3];     // 9216  -> total 48640 B
    int n = blockIdx.x, tid = threadIdx.x;
    for (int i=tid;i<2944;i+=256) xs[i] = g_s2[n*2944+i];
    for (int i=tid;i<9216;i+=256) ws[i] = w[i];
    __syncthreads();
    for (int t=tid;t<720;t+=256){       // 48 c-tiles x 15 l-tiles (3 pooled l each)
        int c = t % 48, lt = t / 48;
        int l0 = lt*3, px = 2*l0;
        float acc0[6]={0,0,0,0,0,0}, acc1[6]={0,0,0,0,0,0};
        for (int ci=0; ci<32; ci++){
            const float* xp = xs + ci*92 + px;
            float xv[8];
            #pragma unroll
            for (int q=0;q<8;q++) xv[q]=xp[q];
            const float* wp = ws + (2*c*32+ci)*3;
            const float* wq = ws + ((2*c+1)*32+ci)*3;
            float wa0=wp[0],wa1=wp[1],wa2=wp[2];
            float wb0=wq[0],wb1=wq[1],wb2=wq[2];
            #pragma unroll
            for (int p=0;p<6;p++){
                acc0[p] = fmaf(xv[p],wa0,fmaf(xv[p+1],wa1,fmaf(xv[p+2],wa2,acc0[p])));
                acc1[p] = fmaf(xv[p],wb0,fmaf(xv[p+1],wb1,fmaf(xv[p+2],wb2,acc1[p])));
            }
        }
        int c0=2*c, c1=2*c+1;
        float a0=__ldg(g+c0)*BN_S, a1=__ldg(g+c1)*BN_S;
        float b0=fmaf(__ldg(cb+c0),a0,__ldg(bb+c0));
        float b1=fmaf(__ldg(cb+c1),a1,__ldg(bb+c1));
        #pragma unroll
        for (int q=0;q<3;q++){
            float v = fmaxf(fmaxf(leaky(fmaf(acc0[2*q],a0,b0)), leaky(fmaf(acc0[2*q+1],a0,b0))),
                            fmaxf(leaky(fmaf(acc1[2*q],a1,b1)), leaky(fmaf(acc1[2*q+1],a1,b1))));
            g_s3[(n*48+c)*45 + l0+q] = v;
        }
    }
}

// ============================================================
// K4: feats = s3(4050,2160) @ fe_fc_w(2160,32) + b. thread per (n,o).
// ============================================================
__global__ void k4(const float* __restrict__ w, const float* __restrict__ b){
    int idx = blockIdx.x*blockDim.x + threadIdx.x;
    if (idx >= NROWS*32) return;
    int n = idx >> 5, o = idx & 31;
    const float* h = g_s3 + n*2160;
    float acc = b[o];
    #pragma unroll 4
    for (int k=0;k<2160;k++) acc = fmaf(h[k], w[k*32+o], acc);
    g_feats[idx] = acc;
}

// ============================================================
// K5: all-pairs gather + 4-layer sim MLP + tanh. thread per (batch,pair).
// ============================================================
__global__ void k5(const float* __restrict__ w1, const float* __restrict__ b1,
                   const float* __restrict__ w2, const float* __restrict__ b2,
                   const float* __restrict__ w3, const float* __restrict__ b3,
                   const float* __restrict__ w4, const float* __restrict__ b4){
    __shared__ float w1s[2048], w2s[512], w3s[128], w4s[8];
    __shared__ float b1s[32], b2s[16], b3s[8], b4s;
    int tid = threadIdx.x;
    for (int i=tid;i<2048;i+=256) w1s[i]=w1[i];
    for (int i=tid;i<512;i+=256)  w2s[i]=w2[i];
    if (tid<128) w3s[tid]=w3[tid];
    if (tid<32)  b1s[tid]=b1[tid];
    if (tid<16)  b2s[tid]=b2[tid];
    if (tid<8)   { w4s[tid]=w4[tid]; b3s[tid]=b3[tid]; }
    if (tid==0)  b4s=b4[0];
    __syncthreads();
    int idx = blockIdx.x*blockDim.x + tid;
    if (idx >= NB*NPAIRS) return;
    int b = idx / NPAIRS, p = idx % NPAIRS;
    // unordered-pair index -> (i,j), S(i)=i*(269-i)/2
    int i = (int)((269.0f - sqrtf(72361.0f - 8.0f*(float)p)) * 0.5f);
    if (i < 0) i = 0; if (i > 133) i = 133;
    while (i > 0   && (i*(269-i))/2 > p) i--;
    while (i < 133 && ((i+1)*(268-i))/2 <= p) i++;
    int j = i + 1 + (p - (i*(269-i))/2);
    const float* fi = g_feats + (b*135+i)*32;
    const float* fj = g_feats + (b*135+j)*32;
    float h1[32];
    #pragma unroll
    for (int o=0;o<32;o++) h1[o]=b1s[o];
    #pragma unroll
    for (int t=0;t<32;t++){ float v = __ldg(fi+t);
        #pragma unroll
        for (int o=0;o<32;o++) h1[o] = fmaf(v, w1s[t*32+o], h1[o]); }
    #pragma unroll
    for (int t=0;t<32;t++){ float v = __ldg(fj+t);
        #pragma unroll
        for (int o=0;o<32;o++) h1[o] = fmaf(v, w1s[(32+t)*32+o], h1[o]); }
    #pragma unroll
    for (int o=0;o<32;o++) h1[o] = fmaxf(h1[o], 0.f);
    float h2[16];
    #pragma unroll
    for (int o=0;o<16;o++) h2[o]=b2s[o];
    #pragma unroll
    for (int t=0;t<32;t++){
        #pragma unroll
        for (int o=0;o<16;o++) h2[o] = fmaf(h1[t], w2s[t*16+o], h2[o]); }
    #pragma unroll
    for (int o=0;o<16;o++) h2[o] = fmaxf(h2[o], 0.f);
    float h3[8];
    #pragma unroll
    for (int o=0;o<8;o++) h3[o]=b3s[o];
    #pragma unroll
    for (int t=0;t<16;t++){
        #pragma unroll
        for (int o=0;o<8;o++) h3[o] = fmaf(h2[t], w3s[t*8+o], h3[o]); }
    float o4 = b4s;
    #pragma unroll
    for (int t=0;t<8;t++) o4 = fmaf(fmaxf(h3[t],0.f), w4s[t], o4);
    g_subj[idx] = tanhf(o4);
}

// ============================================================
// K6a: split-K GEMM partials: (30,9045)@(9045,1024)
// grid (32 n-tiles, 8 k-splits), block 256 = 32 n-lanes x 8 k-groups
// ============================================================
__global__ void k6a(const float* __restrict__ w){
    __shared__ float ssub[30*128];   // subjects chunk
    __shared__ float red[256*30];    // per-thread partials
    int tid = threadIdx.x;
    int lane = tid & 31, kg = tid >> 5;
    int n = blockIdx.x*32 + lane;
    int kstart = blockIdx.y*1131;
    int kend = min(9045, kstart+1131);
    float acc[30];
    #pragma unroll
    for (int m=0;m<30;m++) acc[m]=0.f;
    for (int k0=kstart;k0<kend;k0+=128){
        int clen = min(128, kend-k0);
        __syncthreads();
        for (int i=tid;i<30*128;i+=256){
            int m=i>>7, kk=i&127;
            ssub[i] = (kk<clen) ? g_subj[m*9045 + k0+kk] : 0.f;
        }
        __syncthreads();
        for (int kk=kg; kk<clen; kk+=8){
            float wv = w[(k0+kk)*1024 + n];
            #pragma unroll
            for (int m=0;m<30;m++) acc[m] = fmaf(ssub[m*128+kk], wv, acc[m]);
        }
    }
    __syncthreads();
    #pragma unroll
    for (int m=0;m<30;m++) red[tid*30+m] = acc[m];
    __syncthreads();
    for (int mm=tid; mm<30*32; mm+=256){
        int m = mm>>5, l2 = mm&31;
        float s = 0.f;
        #pragma unroll
        for (int q=0;q<8;q++) s += red[(q*32+l2)*30+m];
        g_part[(blockIdx.y*30+m)*1024 + blockIdx.x*32 + l2] = s;
    }
}

// K6b: reduce split-K + bias + eval-RReLU
__global__ void k6b(const float* __restrict__ b){
    int idx = blockIdx.x*blockDim.x+threadIdx.x;
    if (idx >= 30*1024) return;
    int m = idx>>10, o = idx&1023;
    float s = b[o];
    #pragma unroll
    for (int q=0;q<8;q++) s += g_part[(q*30+m)*1024+o];
    g_c1[idx] = (s >= 0.f) ? s : RRELU_S*s;
}

// K6c: (30,1024)@(1024,256) + relu
__global__ void k6c(const float* __restrict__ w, const float* __restrict__ b){
    int idx = blockIdx.x*blockDim.x+threadIdx.x;
    if (idx >= 30*256) return;
    int m = idx>>8, o = idx&255;
    const float* c1 = g_c1 + m*1024;
    float acc = b[o];
    #pragma unroll 4
    for (int k=0;k<1024;k++) acc = fmaf(c1[k], w[k*256+o], acc);
    g_c2[idx] = fmaxf(acc, 0.f);
}

// K6d: (30,256)@(256,64) + relu
__global__ void k6d(const float* __restrict__ w, const float* __restrict__ b){
    int idx = blockIdx.x*blockDim.x+threadIdx.x;
    if (idx >= 30*64) return;
    int m = idx>>6, o = idx&63;
    const float* c2 = g_c2 + m*256;
    float acc = b[o];
    #pragma unroll 4
    for (int k=0;k<256;k++) acc = fmaf(c2[k], w[k*64+o], acc);
    g_c3[idx] = fmaxf(acc, 0.f);
}

// K6e: (30,64)@(64,3) + log_softmax
__global__ void k6e(const float* __restrict__ w, const float* __restrict__ b,
                    float* __restrict__ out){
    int m = threadIdx.x;
    if (m >= 30) return;
    float v[3];
    #pragma unroll
    for (int c=0;c<3;c++){
        float acc = b[c];
        #pragma unroll
        for (int k=0;k<64;k++) acc = fmaf(g_c3[m*64+k], w[k*3+c], acc);
        v[c]=acc;
    }
    float mx = fmaxf(v[0], fmaxf(v[1],v[2]));
    float lse = mx + logf(expf(v[0]-mx)+expf(v[1]-mx)+expf(v[2]-mx));
    #pragma unroll
    for (int c=0;c<3;c++) out[m*3+c] = v[c]-lse;
}

extern "C" void kernel_launch(void* const* d_in, const int* in_sizes, int n_in,
                              void* d_out, int out_size){
    const float* x      = (const float*)d_in[0];
    const float* c1w    = (const float*)d_in[1];
    const float* c1b    = (const float*)d_in[2];
    const float* bn1g   = (const float*)d_in[3];
    const float* bn1b   = (const float*)d_in[4];
    const float* c2w    = (const float*)d_in[5];
    const float* c2b    = (const float*)d_in[6];
    const float* bn2g   = (const float*)d_in[7];
    const float* bn2b   = (const float*)d_in[8];
    const float* c3w    = (const float*)d_in[9];
    const float* c3b    = (const float*)d_in[10];
    const float* bn3g   = (const float*)d_in[11];
    const float* bn3b   = (const float*)d_in[12];
    const float* few    = (const float*)d_in[13];
    const float* feb    = (const float*)d_in[14];
    const float* s1w    = (const float*)d_in[15];
    const float* s1b    = (const float*)d_in[16];
    const float* s2w    = (const float*)d_in[17];
    const float* s2b    = (const float*)d_in[18];
    const float* s3w    = (const float*)d_in[19];
    const float* s3b    = (const float*)d_in[20];
    const float* s4w    = (const float*)d_in[21];
    const float* s4b    = (const float*)d_in[22];
    const float* clw1   = (const float*)d_in[23];
    const float* clb1   = (const float*)d_in[24];
    const float* clw2   = (const float*)d_in[25];
    const float* clb2   = (const float*)d_in[26];
    const float* clw3   = (const float*)d_in[27];
    const float* clb3   = (const float*)d_in[28];
    const float* clw4   = (const float*)d_in[29];
    const float* clb4   = (const float*)d_in[30];
    float* out = (float*)d_out;

    k1<<<(NROWS*186 + 255)/256, 256>>>(x, c1w, c1b, bn1g, bn1b);
    k2<<<NROWS, 256>>>(c2w, c2b, bn2g, bn2b);
    k3<<<NROWS, 256>>>(c3w, c3b, bn3g, bn3b);
    k4<<<(NROWS*32 + 255)/256, 256>>>(few, feb);
    k5<<<(NB*NPAIRS + 255)/256, 256>>>(s1w,s1b,s2w,s2b,s3w,s3b,s4w,s4b);
    dim3 g6a(32, 8);
    k6a<<<g6a, 256>>>(clw1);
    k6b<<<(30*1024 + 255)/256, 256>>>(clb1);
    k6c<<<(30*256 + 255)/256, 256>>>(clw2, clb2);
    k6d<<<(30*64 + 255)/256, 256>>>(clw3, clb3);
    k6e<<<1, 32>>>(clw4, clb4, out);
}

// round 2
// speedup vs baseline: 3.8696x; 3.8696x over previous
#include <cuda_runtime.h>
#include <math.h>

#define NB 30
#define NODES 135
#define NROWS (NB*NODES)     // 4050
#define NPAIRS 9045

#define BN_S 0.9999950001f   // 1/sqrt(1+1e-5)
#define RRELU_S 0.2291666667f

// ---- scratch (static device globals; no allocation) ----
__device__ float g_s1[NROWS*16*186];   // after stage1: (4050,16,186)
__device__ float g_s2[NROWS*32*92];    // after stage2: (4050,32,92)
__device__ float g_s3[NROWS*48*45];    // after stage3: (4050,48,45) == (4050,2160)
__device__ float g_feats[NROWS*32];    // (4050,32)
__device__ float g_subj[NB*NPAIRS];    // (30,9045)
__device__ float g_part[8*NB*1024];    // split-K partials
__device__ float g_c1[NB*1024];
__device__ float g_c2[NB*256];
__device__ float g_c3[NB*64];

__device__ __forceinline__ float leaky(float v){ return v > 0.f ? v : 0.01f*v; }

// ============================================================
// K1: conv1(1->32,k3) + BN + leaky + pool(2x2 over C,L) -> (4050,16,186)
// ============================================================
__global__ void k1(const float* __restrict__ x, const float* __restrict__ w,
                   const float* __restrict__ cb, const float* __restrict__ g,
                   const float* __restrict__ bb) {
    __shared__ float ws[96], As[32], Bs[32];
    int tid = threadIdx.x;
    if (tid < 96) ws[tid] = w[tid];
    if (tid < 32) { float a = g[tid]*BN_S; As[tid]=a; Bs[tid]=fmaf(cb[tid],a,bb[tid]); }
    __syncthreads();
    int idx = blockIdx.x*blockDim.x + tid;
    if (idx >= NROWS*186) return;
    int n = idx / 186, l = idx % 186;
    const float* xp = x + n*375 + 2*l;
    float x0=xp[0], x1=xp[1], x2=xp[2], x3=xp[3];
    #pragma unroll
    for (int c=0;c<16;c++){
        int c0=2*c, c1=2*c+1;
        float wa0=ws[c0*3],wa1=ws[c0*3+1],wa2=ws[c0*3+2];
        float wb0=ws[c1*3],wb1=ws[c1*3+1],wb2=ws[c1*3+2];
        float p00 = x0*wa0 + x1*wa1 + x2*wa2;
        float p01 = x1*wa0 + x2*wa1 + x3*wa2;
        float p10 = x0*wb0 + x1*wb1 + x2*wb2;
        float p11 = x1*wb0 + x2*wb1 + x3*wb2;
        float a0=As[c0],b0=Bs[c0],a1=As[c1],b1=Bs[c1];
        float v = fmaxf(fmaxf(leaky(fmaf(p00,a0,b0)), leaky(fmaf(p01,a0,b0))),
                        fmaxf(leaky(fmaf(p10,a1,b1)), leaky(fmaf(p11,a1,b1))));
        g_s1[(n*16+c)*186 + l] = v;
    }
}

// ============================================================
// K2: conv2(16->64,k3)+BN+leaky+pool -> (4050,32,92). block per row.
// Weights in even/odd split smem arrays, row stride 49 (odd) -> conflict-free.
// ============================================================
__global__ void k2(const float* __restrict__ w, const float* __restrict__ cb,
                   const float* __restrict__ g, const float* __restrict__ bb){
    __shared__ float xs[16*186];        // 2976
    __shared__ float wse[32*49];        // even out-channels, [c*49 + (ci*3+tap)]
    __shared__ float wso[32*49];        // odd  out-channels
    __shared__ float As[64], Bs[64];
    int n = blockIdx.x, tid = threadIdx.x;
    for (int i=tid;i<16*186;i+=256) xs[i] = g_s1[n*(16*186)+i];
    for (int i=tid;i<1536;i+=256){
        int c = i/48, r = i%48;
        wse[c*49+r] = w[(2*c)*48 + r];
        wso[c*49+r] = w[(2*c+1)*48 + r];
    }
    if (tid<64){ float a=g[tid]*BN_S; As[tid]=a; Bs[tid]=fmaf(cb[tid],a,bb[tid]); }
    __syncthreads();
    for (int t=tid;t<736;t+=256){       // 32 c x 23 l-tiles (4 pooled l each)
        int c = t & 31, lt = t >> 5;
        int l0 = lt*4, px = 2*l0;
        float acc0[8]={0,0,0,0,0,0,0,0}, acc1[8]={0,0,0,0,0,0,0,0};
        const float* we = wse + c*49;
        const float* wo = wso + c*49;
        for (int ci=0; ci<16; ci++){
            const float* xp = xs + ci*186 + px;
            float xv[10];
            #pragma unroll
            for (int q=0;q<10;q++) xv[q]=xp[q];
            float wa0=we[ci*3],wa1=we[ci*3+1],wa2=we[ci*3+2];
            float wb0=wo[ci*3],wb1=wo[ci*3+1],wb2=wo[ci*3+2];
            #pragma unroll
            for (int p=0;p<8;p++){
                acc0[p] = fmaf(xv[p],wa0,fmaf(xv[p+1],wa1,fmaf(xv[p+2],wa2,acc0[p])));
                acc1[p] = fmaf(xv[p],wb0,fmaf(xv[p+1],wb1,fmaf(xv[p+2],wb2,acc1[p])));
            }
        }
        float a0=As[2*c],b0=Bs[2*c],a1=As[2*c+1],b1=Bs[2*c+1];
        #pragma unroll
        for (int q=0;q<4;q++){
            float v = fmaxf(fmaxf(leaky(fmaf(acc0[2*q],a0,b0)), leaky(fmaf(acc0[2*q+1],a0,b0))),
                            fmaxf(leaky(fmaf(acc1[2*q],a1,b1)), leaky(fmaf(acc1[2*q+1],a1,b1))));
            g_s2[(n*32+c)*92 + l0+q] = v;
        }
    }
}

// ============================================================
// K3: conv3(32->96,k3)+BN+leaky+pool -> (4050,48,45). block per row.
// Weights even/odd split, row stride 97 (odd) -> conflict-free.
// Static smem = (2944 + 2*4656)*4 = 49024 B (fits 48KB static limit).
// ============================================================
__global__ void k3(const float* __restrict__ w, const float* __restrict__ cb,
                   const float* __restrict__ g, const float* __restrict__ bb){
    __shared__ float xs[32*92];         // 2944
    __shared__ float wse[48*97];        // [c*97 + (ci*3+tap)]
    __shared__ float wso[48*97];
    int n = blockIdx.x, tid = threadIdx.x;
    for (int i=tid;i<2944;i+=256) xs[i] = g_s2[n*2944+i];
    for (int i=tid;i<4608;i+=256){
        int c = i/96, r = i%96;
        wse[c*97+r] = w[(2*c)*96 + r];
        wso[c*97+r] = w[(2*c+1)*96 + r];
    }
    __syncthreads();
    for (int t=tid;t<720;t+=256){       // 48 c x 15 l-tiles (3 pooled l each)
        int c = t % 48, lt = t / 48;
        int l0 = lt*3, px = 2*l0;
        float acc0[6]={0,0,0,0,0,0}, acc1[6]={0,0,0,0,0,0};
        const float* we = wse + c*97;
        const float* wo = wso + c*97;
        for (int ci=0; ci<32; ci++){
            const float* xp = xs + ci*92 + px;
            float xv[8];
            #pragma unroll
            for (int q=0;q<8;q++) xv[q]=xp[q];
            float wa0=we[ci*3],wa1=we[ci*3+1],wa2=we[ci*3+2];
            float wb0=wo[ci*3],wb1=wo[ci*3+1],wb2=wo[ci*3+2];
            #pragma unroll
            for (int p=0;p<6;p++){
                acc0[p] = fmaf(xv[p],wa0,fmaf(xv[p+1],wa1,fmaf(xv[p+2],wa2,acc0[p])));
                acc1[p] = fmaf(xv[p],wb0,fmaf(xv[p+1],wb1,fmaf(xv[p+2],wb2,acc1[p])));
            }
        }
        int c0=2*c, c1=2*c+1;
        float a0=__ldg(g+c0)*BN_S, a1=__ldg(g+c1)*BN_S;
        float b0=fmaf(__ldg(cb+c0),a0,__ldg(bb+c0));
        float b1=fmaf(__ldg(cb+c1),a1,__ldg(bb+c1));
        #pragma unroll
        for (int q=0;q<3;q++){
            float v = fmaxf(fmaxf(leaky(fmaf(acc0[2*q],a0,b0)), leaky(fmaf(acc0[2*q+1],a0,b0))),
                            fmaxf(leaky(fmaf(acc1[2*q],a1,b1)), leaky(fmaf(acc1[2*q+1],a1,b1))));
            g_s3[(n*48+c)*45 + l0+q] = v;
        }
    }
}

// ============================================================
// K4: feats = s3(4050,2160) @ fe_fc_w(2160,32) + b -- smem-tiled GEMM.
// Block: 64 rows x 32 cols; thread (o=tid&31, ng=tid>>5) owns 8 rows.
// ============================================================
__global__ void k4(const float* __restrict__ w, const float* __restrict__ b){
    __shared__ float hs[64*48];         // [row*48 + kk]
    __shared__ float wsm[48*32];        // [kk*32 + o]
    int tid = threadIdx.x, o = tid & 31, ng = tid >> 5;
    int n0 = blockIdx.x * 64;
    float acc[8] = {0,0,0,0,0,0,0,0};
    for (int k0 = 0; k0 < 2160; k0 += 48){
        __syncthreads();
        for (int i = tid; i < 64*48; i += 256){
            int r = i / 48, kk = i % 48;
            int n = n0 + r;
            hs[i] = (n < NROWS) ? g_s3[n*2160 + k0 + kk] : 0.f;
        }
        for (int i = tid; i < 48*32; i += 256)
            wsm[i] = w[(k0 + (i>>5))*32 + (i&31)];
        __syncthreads();
        #pragma unroll
        for (int kk = 0; kk < 48; kk += 2){
            float wv0 = wsm[kk*32 + o], wv1 = wsm[(kk+1)*32 + o];
            #pragma unroll
            for (int j = 0; j < 8; j++){
                float2 hv = *(const float2*)&hs[(ng*8+j)*48 + kk];
                acc[j] = fmaf(hv.y, wv1, fmaf(hv.x, wv0, acc[j]));
            }
        }
    }
    float bo = b[o];
    #pragma unroll
    for (int j = 0; j < 8; j++){
        int n = n0 + ng*8 + j;
        if (n < NROWS) g_feats[n*32 + o] = acc[j] + bo;
    }
}

// ============================================================
// K5: all-pairs gather + 4-layer sim MLP + tanh. thread per (batch,pair).
// ============================================================
__global__ void k5(const float* __restrict__ w1, const float* __restrict__ b1,
                   const float* __restrict__ w2, const float* __restrict__ b2,
                   const float* __restrict__ w3, const float* __restrict__ b3,
                   const float* __restrict__ w4, const float* __restrict__ b4){
    __shared__ float w1s[2048], w2s[512], w3s[128], w4s[8];
    __shared__ float b1s[32], b2s[16], b3s[8], b4s;
    int tid = threadIdx.x;
    for (int i=tid;i<2048;i+=256) w1s[i]=w1[i];
    for (int i=tid;i<512;i+=256)  w2s[i]=w2[i];
    if (tid<128) w3s[tid]=w3[tid];
    if (tid<32)  b1s[tid]=b1[tid];
    if (tid<16)  b2s[tid]=b2[tid];
    if (tid<8)   { w4s[tid]=w4[tid]; b3s[tid]=b3[tid]; }
    if (tid==0)  b4s=b4[0];
    __syncthreads();
    int idx = blockIdx.x*blockDim.x + tid;
    if (idx >= NB*NPAIRS) return;
    int b = idx / NPAIRS, p = idx % NPAIRS;
    int i = (int)((269.0f - sqrtf(72361.0f - 8.0f*(float)p)) * 0.5f);
    if (i < 0) i = 0; if (i > 133) i = 133;
    while (i > 0   && (i*(269-i))/2 > p) i--;
    while (i < 133 && ((i+1)*(268-i))/2 <= p) i++;
    int j = i + 1 + (p - (i*(269-i))/2);
    const float* fi = g_feats + (b*135+i)*32;
    const float* fj = g_feats + (b*135+j)*32;
    const float2* w1s2 = (const float2*)w1s;
    const float2* w2s2 = (const float2*)w2s;
    float h1[32];
    #pragma unroll
    for (int o=0;o<32;o++) h1[o]=b1s[o];
    #pragma unroll
    for (int t=0;t<32;t++){
        float v = __ldg(fi+t);
        #pragma unroll
        for (int o2=0;o2<16;o2++){
            float2 ww = w1s2[t*16+o2];
            h1[2*o2]   = fmaf(v, ww.x, h1[2*o2]);
            h1[2*o2+1] = fmaf(v, ww.y, h1[2*o2+1]);
        }
    }
    #pragma unroll
    for (int t=0;t<32;t++){
        float v = __ldg(fj+t);
        #pragma unroll
        for (int o2=0;o2<16;o2++){
            float2 ww = w1s2[(32+t)*16+o2];
            h1[2*o2]   = fmaf(v, ww.x, h1[2*o2]);
            h1[2*o2+1] = fmaf(v, ww.y, h1[2*o2+1]);
        }
    }
    #pragma unroll
    for (int o=0;o<32;o++) h1[o] = fmaxf(h1[o], 0.f);
    float h2[16];
    #pragma unroll
    for (int o=0;o<16;o++) h2[o]=b2s[o];
    #pragma unroll
    for (int t=0;t<32;t++){
        #pragma unroll
        for (int o2=0;o2<8;o2++){
            float2 ww = w2s2[t*8+o2];
            h2[2*o2]   = fmaf(h1[t], ww.x, h2[2*o2]);
            h2[2*o2+1] = fmaf(h1[t], ww.y, h2[2*o2+1]);
        }
    }
    #pragma unroll
    for (int o=0;o<16;o++) h2[o] = fmaxf(h2[o], 0.f);
    float h3[8];
    #pragma unroll
    for (int o=0;o<8;o++) h3[o]=b3s[o];
    #pragma unroll
    for (int t=0;t<16;t++){
        #pragma unroll
        for (int o=0;o<8;o++) h3[o] = fmaf(h2[t], w3s[t*8+o], h3[o]);
    }
    float o4 = b4s;
    #pragma unroll
    for (int t=0;t<8;t++) o4 = fmaf(fmaxf(h3[t],0.f), w4s[t], o4);
    g_subj[idx] = tanhf(o4);
}

// ============================================================
// K6a: split-K GEMM partials: (30,9045)@(9045,1024)
// ============================================================
__global__ void k6a(const float* __restrict__ w){
    __shared__ float ssub[30*128];
    __shared__ float red[256*30];
    int tid = threadIdx.x;
    int lane = tid & 31, kg = tid >> 5;
    int n = blockIdx.x*32 + lane;
    int kstart = blockIdx.y*1131;
    int kend = min(9045, kstart+1131);
    float acc[30];
    #pragma unroll
    for (int m=0;m<30;m++) acc[m]=0.f;
    for (int k0=kstart;k0<kend;k0+=128){
        int clen = min(128, kend-k0);
        __syncthreads();
        for (int i=tid;i<30*128;i+=256){
            int m=i>>7, kk=i&127;
            ssub[i] = (kk<clen) ? g_subj[m*9045 + k0+kk] : 0.f;
        }
        __syncthreads();
        for (int kk=kg; kk<clen; kk+=8){
            float wv = w[(k0+kk)*1024 + n];
            #pragma unroll
            for (int m=0;m<30;m++) acc[m] = fmaf(ssub[m*128+kk], wv, acc[m]);
        }
    }
    __syncthreads();
    #pragma unroll
    for (int m=0;m<30;m++) red[tid*30+m] = acc[m];
    __syncthreads();
    for (int mm=tid; mm<30*32; mm+=256){
        int m = mm>>5, l2 = mm&31;
        float s = 0.f;
        #pragma unroll
        for (int q=0;q<8;q++) s += red[(q*32+l2)*30+m];
        g_part[(blockIdx.y*30+m)*1024 + blockIdx.x*32 + l2] = s;
    }
}

__global__ void k6b(const float* __restrict__ b){
    int idx = blockIdx.x*blockDim.x+threadIdx.x;
    if (idx >= 30*1024) return;
    int m = idx>>10, o = idx&1023;
    float s = b[o];
    #pragma unroll
    for (int q=0;q<8;q++) s += g_part[(q*30+m)*1024+o];
    g_c1[idx] = (s >= 0.f) ? s : RRELU_S*s;
}

__global__ void k6c(const float* __restrict__ w, const float* __restrict__ b){
    int idx = blockIdx.x*blockDim.x+threadIdx.x;
    if (idx >= 30*256) return;
    int m = idx>>8, o = idx&255;
    const float* c1 = g_c1 + m*1024;
    float acc = b[o];
    #pragma unroll 4
    for (int k=0;k<1024;k++) acc = fmaf(c1[k], w[k*256+o], acc);
    g_c2[idx] = fmaxf(acc, 0.f);
}

__global__ void k6d(const float* __restrict__ w, const float* __restrict__ b){
    int idx = blockIdx.x*blockDim.x+threadIdx.x;
    if (idx >= 30*64) return;
    int m = idx>>6, o = idx&63;
    const float* c2 = g_c2 + m*256;
    float acc = b[o];
    #pragma unroll 4
    for (int k=0;k<256;k++) acc = fmaf(c2[k], w[k*64+o], acc);
    g_c3[idx] = fmaxf(acc, 0.f);
}

__global__ void k6e(const float* __restrict__ w, const float* __restrict__ b,
                    float* __restrict__ out){
    int m = threadIdx.x;
    if (m >= 30) return;
    float v[3];
    #pragma unroll
    for (int c=0;c<3;c++){
        float acc = b[c];
        #pragma unroll
        for (int k=0;k<64;k++) acc = fmaf(g_c3[m*64+k], w[k*3+c], acc);
        v[c]=acc;
    }
    float mx = fmaxf(v[0], fmaxf(v[1],v[2]));
    float lse = mx + logf(expf(v[0]-mx)+expf(v[1]-mx)+expf(v[2]-mx));
    #pragma unroll
    for (int c=0;c<3;c++) out[m*3+c] = v[c]-lse;
}

extern "C" void kernel_launch(void* const* d_in, const int* in_sizes, int n_in,
                              void* d_out, int out_size){
    const float* x      = (const float*)d_in[0];
    const float* c1w    = (const float*)d_in[1];
    const float* c1b    = (const float*)d_in[2];
    const float* bn1g   = (const float*)d_in[3];
    const float* bn1b   = (const float*)d_in[4];
    const float* c2w    = (const float*)d_in[5];
    const float* c2b    = (const float*)d_in[6];
    const float* bn2g   = (const float*)d_in[7];
    const float* bn2b   = (const float*)d_in[8];
    const float* c3w    = (const float*)d_in[9];
    const float* c3b    = (const float*)d_in[10];
    const float* bn3g   = (const float*)d_in[11];
    const float* bn3b   = (const float*)d_in[12];
    const float* few    = (const float*)d_in[13];
    const float* feb    = (const float*)d_in[14];
    const float* s1w    = (const float*)d_in[15];
    const float* s1b    = (const float*)d_in[16];
    const float* s2w    = (const float*)d_in[17];
    const float* s2b    = (const float*)d_in[18];
    const float* s3w    = (const float*)d_in[19];
    const float* s3b    = (const float*)d_in[20];
    const float* s4w    = (const float*)d_in[21];
    const float* s4b    = (const float*)d_in[22];
    const float* clw1   = (const float*)d_in[23];
    const float* clb1   = (const float*)d_in[24];
    const float* clw2   = (const float*)d_in[25];
    const float* clb2   = (const float*)d_in[26];
    const float* clw3   = (const float*)d_in[27];
    const float* clb3   = (const float*)d_in[28];
    const float* clw4   = (const float*)d_in[29];
    const float* clb4   = (const float*)d_in[30];
    float* out = (float*)d_out;

    k1<<<(NROWS*186 + 255)/256, 256>>>(x, c1w, c1b, bn1g, bn1b);
    k2<<<NROWS, 256>>>(c2w, c2b, bn2g, bn2b);
    k3<<<NROWS, 256>>>(c3w, c3b, bn3g, bn3b);
    k4<<<64, 256>>>(few, feb);
    k5<<<(NB*NPAIRS + 255)/256, 256>>>(s1w,s1b,s2w,s2b,s3w,s3b,s4w,s4b);
    dim3 g6a(32, 8);
    k6a<<<g6a, 256>>>(clw1);
    k6b<<<(30*1024 + 255)/256, 256>>>(clb1);
    k6c<<<(30*256 + 255)/256, 256>>>(clw2, clb2);
    k6d<<<(30*64 + 255)/256, 256>>>(clw3, clb3);
    k6e<<<1, 32>>>(clw4, clb4, out);
}

// round 3
// speedup vs baseline: 4.8646x; 1.2571x over previous
#include <cuda_runtime.h>
#include <math.h>

#define NB 30
#define NODES 135
#define NROWS (NB*NODES)     // 4050
#define NPAIRS 9045

#define BN_S 0.9999950001f   // 1/sqrt(1+1e-5)
#define RRELU_S 0.2291666667f

typedef unsigned long long u64;

// ---- packed fp32x2 helpers (Blackwell FFMA2 path) ----
__device__ __forceinline__ u64 pk(float lo, float hi){
    u64 r; asm("mov.b64 %0, {%1,%2};" : "=l"(r) : "f"(lo), "f"(hi)); return r;
}
__device__ __forceinline__ void upk(u64 v, float& lo, float& hi){
    asm("mov.b64 {%0,%1}, %2;" : "=f"(lo), "=f"(hi) : "l"(v));
}
__device__ __forceinline__ u64 fma2(u64 a, u64 b, u64 c){
    u64 d; asm("fma.rn.f32x2 %0, %1, %2, %3;" : "=l"(d) : "l"(a), "l"(b), "l"(c)); return d;
}
__device__ __forceinline__ u64 add2(u64 a, u64 b){
    u64 d; asm("add.rn.f32x2 %0, %1, %2;" : "=l"(d) : "l"(a), "l"(b)); return d;
}

// ---- scratch (static device globals; no allocation) ----
__device__ float g_s1[NROWS*16*186];
__device__ float g_s2[NROWS*32*92];
__device__ float g_s3[NROWS*48*45];
__device__ float g_feats[NROWS*32];
__device__ float g_subj[NB*NPAIRS];
__device__ float g_part[8*NB*1024];
__device__ float g_c1[NB*1024];
__device__ float g_c2[NB*256];
__device__ float g_c3[NB*64];

__device__ __forceinline__ float leaky(float v){ return v > 0.f ? v : 0.01f*v; }

// ============================================================
// K1: conv1(1->32,k3) + BN + leaky + pool -> (4050,16,186)
// ============================================================
__global__ void k1(const float* __restrict__ x, const float* __restrict__ w,
                   const float* __restrict__ cb, const float* __restrict__ g,
                   const float* __restrict__ bb) {
    __shared__ float ws[96], As[32], Bs[32];
    int tid = threadIdx.x;
    if (tid < 96) ws[tid] = w[tid];
    if (tid < 32) { float a = g[tid]*BN_S; As[tid]=a; Bs[tid]=fmaf(cb[tid],a,bb[tid]); }
    __syncthreads();
    int idx = blockIdx.x*blockDim.x + tid;
    if (idx >= NROWS*186) return;
    int n = idx / 186, l = idx % 186;
    const float* xp = x + n*375 + 2*l;
    float x0=xp[0], x1=xp[1], x2=xp[2], x3=xp[3];
    #pragma unroll
    for (int c=0;c<16;c++){
        int c0=2*c, c1=2*c+1;
        float wa0=ws[c0*3],wa1=ws[c0*3+1],wa2=ws[c0*3+2];
        float wb0=ws[c1*3],wb1=ws[c1*3+1],wb2=ws[c1*3+2];
        float p00 = x0*wa0 + x1*wa1 + x2*wa2;
        float p01 = x1*wa0 + x2*wa1 + x3*wa2;
        float p10 = x0*wb0 + x1*wb1 + x2*wb2;
        float p11 = x1*wb0 + x2*wb1 + x3*wb2;
        float a0=As[c0],b0=Bs[c0],a1=As[c1],b1=Bs[c1];
        float v = fmaxf(fmaxf(leaky(fmaf(p00,a0,b0)), leaky(fmaf(p01,a0,b0))),
                        fmaxf(leaky(fmaf(p10,a1,b1)), leaky(fmaf(p11,a1,b1))));
        g_s1[(n*16+c)*186 + l] = v;
    }
}

// ============================================================
// K2: conv2(16->64,k3)+BN+leaky+pool -> (4050,32,92). Packed FFMA2:
// even/odd output channels share the x multiplicand.
// ============================================================
__global__ void k2(const float* __restrict__ w, const float* __restrict__ cb,
                   const float* __restrict__ g, const float* __restrict__ bb){
    __shared__ float xs[16*186];        // 11904 B
    __shared__ u64   wp[32*49];         // (even,odd) ch pairs, odd stride
    __shared__ float As[64], Bs[64];
    int n = blockIdx.x, tid = threadIdx.x;
    for (int i=tid;i<16*186;i+=256) xs[i] = g_s1[n*(16*186)+i];
    for (int i=tid;i<1536;i+=256){
        int c = i/48, r = i%48;
        wp[c*49+r] = pk(w[(2*c)*48 + r], w[(2*c+1)*48 + r]);
    }
    if (tid<64){ float a=g[tid]*BN_S; As[tid]=a; Bs[tid]=fmaf(cb[tid],a,bb[tid]); }
    __syncthreads();
    for (int t=tid;t<736;t+=256){       // 32 c-pairs x 23 l-tiles
        int c = t & 31, lt = t >> 5;
        int l0 = lt*4, px = 2*l0;
        u64 accp[8];
        #pragma unroll
        for (int p=0;p<8;p++) accp[p] = 0ULL;
        const u64* wc = wp + c*49;
        for (int ci=0; ci<16; ci++){
            const float2* xp = (const float2*)(xs + ci*186 + px);
            float xv[10];
            #pragma unroll
            for (int q=0;q<5;q++){ float2 v2 = xp[q]; xv[2*q]=v2.x; xv[2*q+1]=v2.y; }
            u64 xd[10];
            #pragma unroll
            for (int q=0;q<10;q++) xd[q] = pk(xv[q],xv[q]);
            u64 w0 = wc[ci*3], w1 = wc[ci*3+1], w2 = wc[ci*3+2];
            #pragma unroll
            for (int p=0;p<8;p++)
                accp[p] = fma2(xd[p],w0, fma2(xd[p+1],w1, fma2(xd[p+2],w2, accp[p])));
        }
        float a0=As[2*c],b0=Bs[2*c],a1=As[2*c+1],b1=Bs[2*c+1];
        #pragma unroll
        for (int q=0;q<4;q++){
            float e0,o0,e1,o1;
            upk(accp[2*q], e0, o0);
            upk(accp[2*q+1], e1, o1);
            float v = fmaxf(fmaxf(leaky(fmaf(e0,a0,b0)), leaky(fmaf(e1,a0,b0))),
                            fmaxf(leaky(fmaf(o0,a1,b1)), leaky(fmaf(o1,a1,b1))));
            g_s2[(n*32+c)*92 + l0+q] = v;
        }
    }
}

// ============================================================
// K3: conv3(32->96,k3)+BN+leaky+pool -> (4050,48,45). Packed FFMA2.
// smem = 11776 + 48*97*8 = 49024 B (< 48KB static limit).
// ============================================================
__global__ void k3(const float* __restrict__ w, const float* __restrict__ cb,
                   const float* __restrict__ g, const float* __restrict__ bb){
    __shared__ float xs[32*92];
    __shared__ u64   wp[48*97];
    int n = blockIdx.x, tid = threadIdx.x;
    for (int i=tid;i<2944;i+=256) xs[i] = g_s2[n*2944+i];
    for (int i=tid;i<4608;i+=256){
        int c = i/96, r = i%96;
        wp[c*97+r] = pk(w[(2*c)*96 + r], w[(2*c+1)*96 + r]);
    }
    __syncthreads();
    for (int t=tid;t<720;t+=256){       // 48 c-pairs x 15 l-tiles
        int c = t % 48, lt = t / 48;
        int l0 = lt*3, px = 2*l0;
        u64 accp[6];
        #pragma unroll
        for (int p=0;p<6;p++) accp[p] = 0ULL;
        const u64* wc = wp + c*97;
        for (int ci=0; ci<32; ci++){
            const float2* xp = (const float2*)(xs + ci*92 + px);
            float xv[8];
            #pragma unroll
            for (int q=0;q<4;q++){ float2 v2 = xp[q]; xv[2*q]=v2.x; xv[2*q+1]=v2.y; }
            u64 xd[8];
            #pragma unroll
            for (int q=0;q<8;q++) xd[q] = pk(xv[q],xv[q]);
            u64 w0 = wc[ci*3], w1 = wc[ci*3+1], w2 = wc[ci*3+2];
            #pragma unroll
            for (int p=0;p<6;p++)
                accp[p] = fma2(xd[p],w0, fma2(xd[p+1],w1, fma2(xd[p+2],w2, accp[p])));
        }
        int c0=2*c, c1=2*c+1;
        float a0=__ldg(g+c0)*BN_S, a1=__ldg(g+c1)*BN_S;
        float b0=fmaf(__ldg(cb+c0),a0,__ldg(bb+c0));
        float b1=fmaf(__ldg(cb+c1),a1,__ldg(bb+c1));
        #pragma unroll
        for (int q=0;q<3;q++){
            float e0,o0,e1,o1;
            upk(accp[2*q], e0, o0);
            upk(accp[2*q+1], e1, o1);
            float v = fmaxf(fmaxf(leaky(fmaf(e0,a0,b0)), leaky(fmaf(e1,a0,b0))),
                            fmaxf(leaky(fmaf(o0,a1,b1)), leaky(fmaf(o1,a1,b1))));
            g_s3[(n*48+c)*45 + l0+q] = v;
        }
    }
}

// ============================================================
// K4: feats = s3(4050,2160) @ W(2160,32) + b. 127 blocks x 32 rows.
// Thread (o2=tid&15, rg=tid>>4) -> 2 rows x 1 o-pair, packed accs.
// h broadcast-duplicated in smem; W packed by o-pair.
// ============================================================
__global__ void k4(const float* __restrict__ w, const float* __restrict__ b){
    __shared__ u64 hs2[32*48];          // pk(h,h), 12288 B
    __shared__ u64 ws2[48*16];          // pk(w[.,2o2],w[.,2o2+1]), 6144 B
    int tid = threadIdx.x, o2 = tid & 15, rg = tid >> 4;
    int n0 = blockIdx.x * 32;
    int r0 = rg*2, r1 = rg*2+1;
    u64 acc0 = 0ULL, acc1 = 0ULL;
    for (int k0 = 0; k0 < 2160; k0 += 48){
        __syncthreads();
        for (int i = tid; i < 32*48; i += 256){
            int r = i / 48, kk = i % 48;
            int n = n0 + r;
            float v = (n < NROWS) ? g_s3[n*2160 + k0 + kk] : 0.f;
            hs2[i] = pk(v, v);
        }
        for (int i = tid; i < 48*16; i += 256){
            int kk = i >> 4, oo = i & 15;
            float2 wv = *(const float2*)(w + (k0+kk)*32 + 2*oo);
            ws2[i] = pk(wv.x, wv.y);
        }
        __syncthreads();
        #pragma unroll
        for (int kk = 0; kk < 48; kk++){
            u64 wv = ws2[kk*16 + o2];
            acc0 = fma2(hs2[r0*48 + kk], wv, acc0);
            acc1 = fma2(hs2[r1*48 + kk], wv, acc1);
        }
    }
    float be = b[2*o2], bo = b[2*o2+1];
    float e,o;
    int n = n0 + r0;
    if (n < NROWS){
        upk(acc0, e, o);
        *(float2*)(g_feats + n*32 + 2*o2) = make_float2(e+be, o+bo);
    }
    n = n0 + r1;
    if (n < NROWS){
        upk(acc1, e, o);
        *(float2*)(g_feats + n*32 + 2*o2) = make_float2(e+be, o+bo);
    }
}

// ============================================================
// K5: all-pairs gather + 4-layer sim MLP + tanh. Packed FFMA2
// over output pairs (activation multiplicand shared).
// ============================================================
__global__ void k5(const float* __restrict__ w1, const float* __restrict__ b1,
                   const float* __restrict__ w2, const float* __restrict__ b2,
                   const float* __restrict__ w3, const float* __restrict__ b3,
                   const float* __restrict__ w4, const float* __restrict__ b4){
    __shared__ u64 w1u[1024], w2u[256], w3u[64];
    __shared__ float w4s[8], b1s[32], b2s[16], b3s[8];
    __shared__ float b4s;
    int tid = threadIdx.x;
    for (int i=tid;i<1024;i+=256){ float2 v = *(const float2*)(w1+2*i); w1u[i]=pk(v.x,v.y); }
    if (tid<256){ float2 v = *(const float2*)(w2+2*tid); w2u[tid]=pk(v.x,v.y); }
    if (tid<64) { float2 v = *(const float2*)(w3+2*tid); w3u[tid]=pk(v.x,v.y); }
    if (tid<32)  b1s[tid]=b1[tid];
    if (tid<16)  b2s[tid]=b2[tid];
    if (tid<8)   { w4s[tid]=w4[tid]; b3s[tid]=b3[tid]; }
    if (tid==0)  b4s=b4[0];
    __syncthreads();
    int idx = blockIdx.x*blockDim.x + tid;
    if (idx >= NB*NPAIRS) return;
    int b = idx / NPAIRS, p = idx % NPAIRS;
    int i = (int)((269.0f - sqrtf(72361.0f - 8.0f*(float)p)) * 0.5f);
    if (i < 0) i = 0; if (i > 133) i = 133;
    while (i > 0   && (i*(269-i))/2 > p) i--;
    while (i < 133 && ((i+1)*(268-i))/2 <= p) i++;
    int j = i + 1 + (p - (i*(269-i))/2);
    const float* fi = g_feats + (b*135+i)*32;
    const float* fj = g_feats + (b*135+j)*32;
    u64 hp1[16];
    #pragma unroll
    for (int o=0;o<16;o++) hp1[o] = pk(b1s[2*o], b1s[2*o+1]);
    #pragma unroll
    for (int t=0;t<32;t++){
        u64 v2 = pk(__ldg(fi+t), __ldg(fi+t));
        #pragma unroll
        for (int o=0;o<16;o++) hp1[o] = fma2(v2, w1u[t*16+o], hp1[o]);
    }
    #pragma unroll
    for (int t=0;t<32;t++){
        u64 v2 = pk(__ldg(fj+t), __ldg(fj+t));
        #pragma unroll
        for (int o=0;o<16;o++) hp1[o] = fma2(v2, w1u[(32+t)*16+o], hp1[o]);
    }
    float h1[32];
    #pragma unroll
    for (int o=0;o<16;o++){ float e,od; upk(hp1[o],e,od);
        h1[2*o]=fmaxf(e,0.f); h1[2*o+1]=fmaxf(od,0.f); }
    u64 hp2[8];
    #pragma unroll
    for (int o=0;o<8;o++) hp2[o] = pk(b2s[2*o], b2s[2*o+1]);
    #pragma unroll
    for (int t=0;t<32;t++){
        u64 v2 = pk(h1[t], h1[t]);
        #pragma unroll
        for (int o=0;o<8;o++) hp2[o] = fma2(v2, w2u[t*8+o], hp2[o]);
    }
    float h2[16];
    #pragma unroll
    for (int o=0;o<8;o++){ float e,od; upk(hp2[o],e,od);
        h2[2*o]=fmaxf(e,0.f); h2[2*o+1]=fmaxf(od,0.f); }
    u64 hp3[4];
    #pragma unroll
    for (int o=0;o<4;o++) hp3[o] = pk(b3s[2*o], b3s[2*o+1]);
    #pragma unroll
    for (int t=0;t<16;t++){
        u64 v2 = pk(h2[t], h2[t]);
        #pragma unroll
        for (int o=0;o<4;o++) hp3[o] = fma2(v2, w3u[t*4+o], hp3[o]);
    }
    float o4 = b4s;
    #pragma unroll
    for (int o=0;o<4;o++){
        float e,od; upk(hp3[o],e,od);
        o4 = fmaf(fmaxf(e,0.f),  w4s[2*o],   o4);
        o4 = fmaf(fmaxf(od,0.f), w4s[2*o+1], o4);
    }
    g_subj[idx] = tanhf(o4);
}

// ============================================================
// K6a: split-K GEMM partials: (30,9045)@(9045,1024). Packed over
// batch-row pairs (w multiplicand shared). subj chunk transposed
// in smem as pk(m-pair), stride 17 (odd) -> conflict-free.
// ============================================================
__global__ void k6a(const float* __restrict__ w){
    __shared__ u64 ssub2[128*17];       // 17408 B
    __shared__ u64 red[256*15];         // 30720 B
    int tid = threadIdx.x;
    int lane = tid & 31, kg = tid >> 5;
    int n = blockIdx.x*32 + lane;
    int kstart = blockIdx.y*1131;
    int kend = min(9045, kstart+1131);
    u64 accp[15];
    #pragma unroll
    for (int m=0;m<15;m++) accp[m]=0ULL;
    for (int k0=kstart;k0<kend;k0+=128){
        int clen = min(128, kend-k0);
        __syncthreads();
        for (int i=tid;i<15*128;i+=256){
            int m = i>>7, kk = i&127;
            float v0=0.f, v1=0.f;
            if (kk<clen){
                v0 = g_subj[(2*m)*9045 + k0+kk];
                v1 = g_subj[(2*m+1)*9045 + k0+kk];
            }
            ssub2[kk*17+m] = pk(v0,v1);
        }
        __syncthreads();
        for (int kk=kg; kk<clen; kk+=8){
            float wv = w[(k0+kk)*1024 + n];
            u64 wv2 = pk(wv,wv);
            #pragma unroll
            for (int m=0;m<15;m++) accp[m] = fma2(ssub2[kk*17+m], wv2, accp[m]);
        }
    }
    __syncthreads();
    #pragma unroll
    for (int m=0;m<15;m++) red[tid*15+m] = accp[m];
    __syncthreads();
    for (int it=tid; it<32*15; it+=256){
        int l2 = it/15, mp = it%15;
        u64 s = red[l2*15+mp];
        #pragma unroll
        for (int q=1;q<8;q++) s = add2(s, red[(q*32+l2)*15+mp]);
        float e,o; upk(s,e,o);
        g_part[(blockIdx.y*30+2*mp)*1024   + blockIdx.x*32 + l2] = e;
        g_part[(blockIdx.y*30+2*mp+1)*1024 + blockIdx.x*32 + l2] = o;
    }
}

__global__ void k6b(const float* __restrict__ b){
    int idx = blockIdx.x*blockDim.x+threadIdx.x;
    if (idx >= 30*1024) return;
    int m = idx>>10, o = idx&1023;
    float s = b[o];
    #pragma unroll
    for (int q=0;q<8;q++) s += g_part[(q*30+m)*1024+o];
    g_c1[idx] = (s >= 0.f) ? s : RRELU_S*s;
}

__global__ void k6c(const float* __restrict__ w, const float* __restrict__ b){
    int idx = blockIdx.x*blockDim.x+threadIdx.x;
    if (idx >= 30*256) return;
    int m = idx>>8, o = idx&255;
    const float* c1 = g_c1 + m*1024;
    float acc = b[o];
    #pragma unroll 4
    for (int k=0;k<1024;k++) acc = fmaf(c1[k], w[k*256+o], acc);
    g_c2[idx] = fmaxf(acc, 0.f);
}

__global__ void k6d(const float* __restrict__ w, const float* __restrict__ b){
    int idx = blockIdx.x*blockDim.x+threadIdx.x;
    if (idx >= 30*64) return;
    int m = idx>>6, o = idx&63;
    const float* c2 = g_c2 + m*256;
    float acc = b[o];
    #pragma unroll 4
    for (int k=0;k<256;k++) acc = fmaf(c2[k], w[k*64+o], acc);
    g_c3[idx] = fmaxf(acc, 0.f);
}

__global__ void k6e(const float* __restrict__ w, const float* __restrict__ b,
                    float* __restrict__ out){
    int m = threadIdx.x;
    if (m >= 30) return;
    float v[3];
    #pragma unroll
    for (int c=0;c<3;c++){
        float acc = b[c];
        #pragma unroll
        for (int k=0;k<64;k++) acc = fmaf(g_c3[m*64+k], w[k*3+c], acc);
        v[c]=acc;
    }
    float mx = fmaxf(v[0], fmaxf(v[1],v[2]));
    float lse = mx + logf(expf(v[0]-mx)+expf(v[1]-mx)+expf(v[2]-mx));
    #pragma unroll
    for (int c=0;c<3;c++) out[m*3+c] = v[c]-lse;
}

extern "C" void kernel_launch(void* const* d_in, const int* in_sizes, int n_in,
                              void* d_out, int out_size){
    const float* x      = (const float*)d_in[0];
    const float* c1w    = (const float*)d_in[1];
    const float* c1b    = (const float*)d_in[2];
    const float* bn1g   = (const float*)d_in[3];
    const float* bn1b   = (const float*)d_in[4];
    const float* c2w    = (const float*)d_in[5];
    const float* c2b    = (const float*)d_in[6];
    const float* bn2g   = (const float*)d_in[7];
    const float* bn2b   = (const float*)d_in[8];
    const float* c3w    = (const float*)d_in[9];
    const float* c3b    = (const float*)d_in[10];
    const float* bn3g   = (const float*)d_in[11];
    const float* bn3b   = (const float*)d_in[12];
    const float* few    = (const float*)d_in[13];
    const float* feb    = (const float*)d_in[14];
    const float* s1w    = (const float*)d_in[15];
    const float* s1b    = (const float*)d_in[16];
    const float* s2w    = (const float*)d_in[17];
    const float* s2b    = (const float*)d_in[18];
    const float* s3w    = (const float*)d_in[19];
    const float* s3b    = (const float*)d_in[20];
    const float* s4w    = (const float*)d_in[21];
    const float* s4b    = (const float*)d_in[22];
    const float* clw1   = (const float*)d_in[23];
    const float* clb1   = (const float*)d_in[24];
    const float* clw2   = (const float*)d_in[25];
    const float* clb2   = (const float*)d_in[26];
    const float* clw3   = (const float*)d_in[27];
    const float* clb3   = (const float*)d_in[28];
    const float* clw4   = (const float*)d_in[29];
    const float* clb4   = (const float*)d_in[30];
    float* out = (float*)d_out;

    k1<<<(NROWS*186 + 255)/256, 256>>>(x, c1w, c1b, bn1g, bn1b);
    k2<<<NROWS, 256>>>(c2w, c2b, bn2g, bn2b);
    k3<<<NROWS, 256>>>(c3w, c3b, bn3g, bn3b);
    k4<<<127, 256>>>(few, feb);
    k5<<<(NB*NPAIRS + 255)/256, 256>>>(s1w,s1b,s2w,s2b,s3w,s3b,s4w,s4b);
    dim3 g6a(32, 8);
    k6a<<<g6a, 256>>>(clw1);
    k6b<<<(30*1024 + 255)/256, 256>>>(clb1);
    k6c<<<(30*256 + 255)/256, 256>>>(clw2, clb2);
    k6d<<<(30*64 + 255)/256, 256>>>(clw3, clb3);
    k6e<<<1, 32>>>(clw4, clb4, out);
}

// round 4
// speedup vs baseline: 6.4504x; 1.3260x over previous
#include <cuda_runtime.h>
#include <math.h>

#define NB 30
#define NODES 135
#define NROWS (NB*NODES)     // 4050
#define NPAIRS 9045

#define BN_S 0.9999950001f   // 1/sqrt(1+1e-5)
#define RRELU_S 0.2291666667f

#define K4_SPLIT 9           // 2160 = 9 * 240, 240 = 5 chunks of 48
#define K6_SPLIT 16

typedef unsigned long long u64;

// ---- packed fp32x2 helpers (Blackwell FFMA2 path) ----
__device__ __forceinline__ u64 pk(float lo, float hi){
    u64 r; asm("mov.b64 %0, {%1,%2};" : "=l"(r) : "f"(lo), "f"(hi)); return r;
}
__device__ __forceinline__ void upk(u64 v, float& lo, float& hi){
    asm("mov.b64 {%0,%1}, %2;" : "=f"(lo), "=f"(hi) : "l"(v));
}
__device__ __forceinline__ u64 fma2(u64 a, u64 b, u64 c){
    u64 d; asm("fma.rn.f32x2 %0, %1, %2, %3;" : "=l"(d) : "l"(a), "l"(b), "l"(c)); return d;
}
__device__ __forceinline__ u64 add2(u64 a, u64 b){
    u64 d; asm("add.rn.f32x2 %0, %1, %2;" : "=l"(d) : "l"(a), "l"(b)); return d;
}

// ---- scratch (static device globals; no allocation) ----
__device__ float g_s3[NROWS*48*45];          // (4050, 2160)
__device__ float g_feats[NROWS*32];
__device__ float g_subj[NB*NPAIRS];
__device__ float g_p4[K4_SPLIT*NROWS*32];    // k4 split-K partials
__device__ float g_part[K6_SPLIT*NB*1024];
__device__ float g_c1[NB*1024];
__device__ float g_c2[NB*256];
__device__ float g_c3[NB*64];

__device__ __forceinline__ float leaky(float v){ return v > 0.f ? v : 0.01f*v; }

// ============================================================
// KCONV: fused conv1+conv2+conv3 (+BN+leaky+pool each) per row.
// One block per row n. Dynamic smem (49024 B), phase-aliased:
//   phase A: s2s | s1s | wp2      (stage1 + stage2)
//   phase B: s2s | wp3            (stage3)
// ============================================================
__global__ void kconv(const float* __restrict__ x,
                      const float* __restrict__ w1, const float* __restrict__ cb1,
                      const float* __restrict__ g1, const float* __restrict__ bb1,
                      const float* __restrict__ w2, const float* __restrict__ cb2,
                      const float* __restrict__ g2, const float* __restrict__ bb2,
                      const float* __restrict__ w3, const float* __restrict__ cb3,
                      const float* __restrict__ g3, const float* __restrict__ bb3){
    extern __shared__ float dsm[];
    float* s2s = dsm;                           // [0, 2944) floats
    float* s1s = dsm + 2944;                    // [2944, 5920) floats
    u64*   wp2 = (u64*)(dsm + 2944 + 2976);     // byte off 23680, 1568 u64
    u64*   wp3 = (u64*)(dsm + 2944);            // byte off 11776, 4656 u64 (phase B)

    __shared__ float xr[376];
    __shared__ float ws1[96], A1[32], B1[32], A2[64], B2[64];

    int n = blockIdx.x, tid = threadIdx.x;

    // ---- loads for phase A ----
    for (int i=tid;i<375;i+=256) xr[i] = x[n*375+i];
    if (tid < 96) ws1[tid] = w1[tid];
    if (tid < 32){ float a = g1[tid]*BN_S; A1[tid]=a; B1[tid]=fmaf(cb1[tid],a,bb1[tid]); }
    if (tid < 64){ float a = g2[tid]*BN_S; A2[tid]=a; B2[tid]=fmaf(cb2[tid],a,bb2[tid]); }
    for (int i=tid;i<1536;i+=256){
        int c = i/48, r = i%48;
        wp2[c*49+r] = pk(w2[(2*c)*48 + r], w2[(2*c+1)*48 + r]);
    }
    __syncthreads();

    // ---- stage 1: x(375) -> s1s(16,186) ----
    for (int t=tid;t<2976;t+=256){
        int c = t/186, l = t%186;
        float x0=xr[2*l], x1=xr[2*l+1], x2=xr[2*l+2], x3=xr[2*l+3];
        int c0=2*c, c1=2*c+1;
        float wa0=ws1[c0*3],wa1=ws1[c0*3+1],wa2=ws1[c0*3+2];
        float wb0=ws1[c1*3],wb1=ws1[c1*3+1],wb2=ws1[c1*3+2];
        float p00 = x0*wa0 + x1*wa1 + x2*wa2;
        float p01 = x1*wa0 + x2*wa1 + x3*wa2;
        float p10 = x0*wb0 + x1*wb1 + x2*wb2;
        float p11 = x1*wb0 + x2*wb1 + x3*wb2;
        float a0=A1[c0],b0=B1[c0],a1=A1[c1],b1=B1[c1];
        float v = fmaxf(fmaxf(leaky(fmaf(p00,a0,b0)), leaky(fmaf(p01,a0,b0))),
                        fmaxf(leaky(fmaf(p10,a1,b1)), leaky(fmaf(p11,a1,b1))));
        s1s[c*186+l] = v;
    }
    __syncthreads();

    // ---- stage 2: s1s(16,186) -> s2s(32,92), packed FFMA2 ----
    for (int t=tid;t<736;t+=256){
        int c = t & 31, lt = t >> 5;
        int l0 = lt*4, px = 2*l0;
        u64 accp[8];
        #pragma unroll
        for (int p=0;p<8;p++) accp[p] = 0ULL;
        const u64* wc = wp2 + c*49;
        for (int ci=0; ci<16; ci++){
            const float2* xp = (const float2*)(s1s + ci*186 + px);
            float xv[10];
            #pragma unroll
            for (int q=0;q<5;q++){ float2 v2 = xp[q]; xv[2*q]=v2.x; xv[2*q+1]=v2.y; }
            u64 xd[10];
            #pragma unroll
            for (int q=0;q<10;q++) xd[q] = pk(xv[q],xv[q]);
            u64 w0 = wc[ci*3], w1v = wc[ci*3+1], w2v = wc[ci*3+2];
            #pragma unroll
            for (int p=0;p<8;p++)
                accp[p] = fma2(xd[p],w0, fma2(xd[p+1],w1v, fma2(xd[p+2],w2v, accp[p])));
        }
        float a0=A2[2*c],b0=B2[2*c],a1=A2[2*c+1],b1=B2[2*c+1];
        #pragma unroll
        for (int q=0;q<4;q++){
            float e0,o0,e1,o1;
            upk(accp[2*q], e0, o0);
            upk(accp[2*q+1], e1, o1);
            float v = fmaxf(fmaxf(leaky(fmaf(e0,a0,b0)), leaky(fmaf(e1,a0,b0))),
                            fmaxf(leaky(fmaf(o0,a1,b1)), leaky(fmaf(o1,a1,b1))));
            s2s[c*92 + l0+q] = v;
        }
    }
    __syncthreads();

    // ---- phase B weights: wp3 overwrites s1s/wp2 ----
    for (int i=tid;i<4608;i+=256){
        int c = i/96, r = i%96;
        wp3[c*97+r] = pk(w3[(2*c)*96 + r], w3[(2*c+1)*96 + r]);
    }
    __syncthreads();

    // ---- stage 3: s2s(32,92) -> g_s3(n, 48*45), packed FFMA2 ----
    for (int t=tid;t<720;t+=256){
        int c = t % 48, lt = t / 48;
        int l0 = lt*3, px = 2*l0;
        u64 accp[6];
        #pragma unroll
        for (int p=0;p<6;p++) accp[p] = 0ULL;
        const u64* wc = wp3 + c*97;
        for (int ci=0; ci<32; ci++){
            const float2* xp = (const float2*)(s2s + ci*92 + px);
            float xv[8];
            #pragma unroll
            for (int q=0;q<4;q++){ float2 v2 = xp[q]; xv[2*q]=v2.x; xv[2*q+1]=v2.y; }
            u64 xd[8];
            #pragma unroll
            for (int q=0;q<8;q++) xd[q] = pk(xv[q],xv[q]);
            u64 w0 = wc[ci*3], w1v = wc[ci*3+1], w2v = wc[ci*3+2];
            #pragma unroll
            for (int p=0;p<6;p++)
                accp[p] = fma2(xd[p],w0, fma2(xd[p+1],w1v, fma2(xd[p+2],w2v, accp[p])));
        }
        int c0=2*c, c1=2*c+1;
        float a0=__ldg(g3+c0)*BN_S, a1=__ldg(g3+c1)*BN_S;
        float b0=fmaf(__ldg(cb3+c0),a0,__ldg(bb3+c0));
        float b1=fmaf(__ldg(cb3+c1),a1,__ldg(bb3+c1));
        #pragma unroll
        for (int q=0;q<3;q++){
            float e0,o0,e1,o1;
            upk(accp[2*q], e0, o0);
            upk(accp[2*q+1], e1, o1);
            float v = fmaxf(fmaxf(leaky(fmaf(e0,a0,b0)), leaky(fmaf(e1,a0,b0))),
                            fmaxf(leaky(fmaf(o0,a1,b1)), leaky(fmaf(o1,a1,b1))));
            g_s3[(n*48+c)*45 + l0+q] = v;
        }
    }
}

// ============================================================
// K4a: split-K GEMM partials: s3(4050,2160) @ W(2160,32).
// grid (254 row-tiles, 9 k-splits), block 256 = 16 o-pairs x 16 rows.
// Row chunk (48 k) staged in regs via 12 independent float4 LDGs.
// ============================================================
__global__ void k4a(const float* __restrict__ w){
    __shared__ u64 ws2[48*16];          // [kk*16 + o2]
    int tid = threadIdx.x, o2 = tid & 15, r = tid >> 4;
    int n = blockIdx.x*16 + r;
    int nn = n < NROWS ? n : NROWS-1;
    int ks = blockIdx.y*240;
    u64 acc = 0ULL;
    for (int c0 = 0; c0 < 240; c0 += 48){
        __syncthreads();
        for (int i = tid; i < 384; i += 256){
            int kk = i >> 3, j = i & 7;
            float4 f = ((const float4*)(w + (ks + c0 + kk)*32))[j];
            ws2[kk*16 + 2*j]   = pk(f.x, f.y);
            ws2[kk*16 + 2*j+1] = pk(f.z, f.w);
        }
        const float4* hp = (const float4*)(g_s3 + (size_t)nn*2160 + ks + c0);
        float4 hv[12];
        #pragma unroll
        for (int q=0;q<12;q++) hv[q] = hp[q];
        __syncthreads();
        #pragma unroll
        for (int q=0;q<12;q++){
            acc = fma2(pk(hv[q].x,hv[q].x), ws2[(4*q+0)*16+o2], acc);
            acc = fma2(pk(hv[q].y,hv[q].y), ws2[(4*q+1)*16+o2], acc);
            acc = fma2(pk(hv[q].z,hv[q].z), ws2[(4*q+2)*16+o2], acc);
            acc = fma2(pk(hv[q].w,hv[q].w), ws2[(4*q+3)*16+o2], acc);
        }
    }
    if (n < NROWS){
        float e,o; upk(acc,e,o);
        *(float2*)(g_p4 + ((size_t)blockIdx.y*NROWS + n)*32 + 2*o2) = make_float2(e,o);
    }
}

// K4b: reduce split-K partials + bias -> g_feats
__global__ void k4b(const float* __restrict__ b){
    int idx = blockIdx.x*blockDim.x + threadIdx.x;
    if (idx >= NROWS*32) return;
    int o = idx & 31;
    float s = b[o];
    #pragma unroll
    for (int q=0;q<K4_SPLIT;q++) s += g_p4[(size_t)q*NROWS*32 + idx];
    g_feats[idx] = s;
}

// ============================================================
// K5: all-pairs gather + 4-layer sim MLP + tanh. Packed FFMA2,
// float4 feature gathers.
// ============================================================
__global__ void k5(const float* __restrict__ w1, const float* __restrict__ b1,
                   const float* __restrict__ w2, const float* __restrict__ b2,
                   const float* __restrict__ w3, const float* __restrict__ b3,
                   const float* __restrict__ w4, const float* __restrict__ b4){
    __shared__ u64 w1u[1024], w2u[256], w3u[64];
    __shared__ float w4s[8], b1s[32], b2s[16], b3s[8];
    __shared__ float b4s;
    int tid = threadIdx.x;
    for (int i=tid;i<1024;i+=256){ float2 v = *(const float2*)(w1+2*i); w1u[i]=pk(v.x,v.y); }
    if (tid<256){ float2 v = *(const float2*)(w2+2*tid); w2u[tid]=pk(v.x,v.y); }
    if (tid<64) { float2 v = *(const float2*)(w3+2*tid); w3u[tid]=pk(v.x,v.y); }
    if (tid<32)  b1s[tid]=b1[tid];
    if (tid<16)  b2s[tid]=b2[tid];
    if (tid<8)   { w4s[tid]=w4[tid]; b3s[tid]=b3[tid]; }
    if (tid==0)  b4s=b4[0];
    __syncthreads();
    int idx = blockIdx.x*blockDim.x + tid;
    if (idx >= NB*NPAIRS) return;
    int b = idx / NPAIRS, p = idx % NPAIRS;
    int i = (int)((269.0f - sqrtf(72361.0f - 8.0f*(float)p)) * 0.5f);
    if (i < 0) i = 0; if (i > 133) i = 133;
    while (i > 0   && (i*(269-i))/2 > p) i--;
    while (i < 133 && ((i+1)*(268-i))/2 <= p) i++;
    int j = i + 1 + (p - (i*(269-i))/2);
    const float4* fi4 = (const float4*)(g_feats + (b*135+i)*32);
    const float4* fj4 = (const float4*)(g_feats + (b*135+j)*32);
    u64 hp1[16];
    #pragma unroll
    for (int o=0;o<16;o++) hp1[o] = pk(b1s[2*o], b1s[2*o+1]);
    #pragma unroll
    for (int q=0;q<8;q++){
        float4 f = fi4[q];
        float fv[4] = {f.x,f.y,f.z,f.w};
        #pragma unroll
        for (int s=0;s<4;s++){
            u64 v2 = pk(fv[s], fv[s]);
            int t = 4*q+s;
            #pragma unroll
            for (int o=0;o<16;o++) hp1[o] = fma2(v2, w1u[t*16+o], hp1[o]);
        }
    }
    #pragma unroll
    for (int q=0;q<8;q++){
        float4 f = fj4[q];
        float fv[4] = {f.x,f.y,f.z,f.w};
        #pragma unroll
        for (int s=0;s<4;s++){
            u64 v2 = pk(fv[s], fv[s]);
            int t = 32 + 4*q+s;
            #pragma unroll
            for (int o=0;o<16;o++) hp1[o] = fma2(v2, w1u[t*16+o], hp1[o]);
        }
    }
    float h1[32];
    #pragma unroll
    for (int o=0;o<16;o++){ float e,od; upk(hp1[o],e,od);
        h1[2*o]=fmaxf(e,0.f); h1[2*o+1]=fmaxf(od,0.f); }
    u64 hp2[8];
    #pragma unroll
    for (int o=0;o<8;o++) hp2[o] = pk(b2s[2*o], b2s[2*o+1]);
    #pragma unroll
    for (int t=0;t<32;t++){
        u64 v2 = pk(h1[t], h1[t]);
        #pragma unroll
        for (int o=0;o<8;o++) hp2[o] = fma2(v2, w2u[t*8+o], hp2[o]);
    }
    float h2[16];
    #pragma unroll
    for (int o=0;o<8;o++){ float e,od; upk(hp2[o],e,od);
        h2[2*o]=fmaxf(e,0.f); h2[2*o+1]=fmaxf(od,0.f); }
    u64 hp3[4];
    #pragma unroll
    for (int o=0;o<4;o++) hp3[o] = pk(b3s[2*o], b3s[2*o+1]);
    #pragma unroll
    for (int t=0;t<16;t++){
        u64 v2 = pk(h2[t], h2[t]);
        #pragma unroll
        for (int o=0;o<4;o++) hp3[o] = fma2(v2, w3u[t*4+o], hp3[o]);
    }
    float o4 = b4s;
    #pragma unroll
    for (int o=0;o<4;o++){
        float e,od; upk(hp3[o],e,od);
        o4 = fmaf(fmaxf(e,0.f),  w4s[2*o],   o4);
        o4 = fmaf(fmaxf(od,0.f), w4s[2*o+1], o4);
    }
    g_subj[idx] = tanhf(o4);
}

// ============================================================
// K6a: split-K GEMM partials: (30,9045)@(9045,1024).
// W tile staged in smem via float4 (MLP 4, coalesced). 16 k-splits.
// Union smem buffer: [ssub2 | wtile] during loop, [red] after.
// ============================================================
__global__ void k6a(const float* __restrict__ w){
    __shared__ __align__(16) char sbuf[33792];
    u64*   ssub2 = (u64*)sbuf;                 // 128*17 u64 = 17408 B
    float* wt    = (float*)(sbuf + 17408);     // 128*32 f   = 16384 B
    u64*   red   = (u64*)sbuf;                 // 256*15 u64 = 30720 B (post-loop)
    int tid = threadIdx.x;
    int lane = tid & 31, kg = tid >> 5;
    int nb = blockIdx.x*32;
    int kstart = blockIdx.y*566;
    int kend = min(9045, kstart+566);
    u64 accp[15];
    #pragma unroll
    for (int m=0;m<15;m++) accp[m]=0ULL;
    for (int k0=kstart;k0<kend;k0+=128){
        int clen = min(128, kend-k0);
        __syncthreads();
        for (int i=tid;i<15*128;i+=256){
            int m = i>>7, kk = i&127;
            float v0=0.f, v1=0.f;
            if (kk<clen){
                v0 = g_subj[(2*m)*9045 + k0+kk];
                v1 = g_subj[(2*m+1)*9045 + k0+kk];
            }
            ssub2[kk*17+m] = pk(v0,v1);
        }
        for (int i=tid;i<1024;i+=256){
            int kk = i>>3, j = i&7;
            float4 f = make_float4(0.f,0.f,0.f,0.f);
            if (kk < clen)
                f = ((const float4*)(w + (size_t)(k0+kk)*1024 + nb))[j];
            ((float4*)(wt + kk*32))[j] = f;
        }
        __syncthreads();
        for (int kk=kg; kk<clen; kk+=8){
            float wv = wt[kk*32 + lane];
            u64 wv2 = pk(wv,wv);
            #pragma unroll
            for (int m=0;m<15;m++) accp[m] = fma2(ssub2[kk*17+m], wv2, accp[m]);
        }
    }
    __syncthreads();
    #pragma unroll
    for (int m=0;m<15;m++) red[tid*15+m] = accp[m];
    __syncthreads();
    for (int it=tid; it<32*15; it+=256){
        int l2 = it/15, mp = it%15;
        u64 s = red[l2*15+mp];
        #pragma unroll
        for (int q=1;q<8;q++) s = add2(s, red[(q*32+l2)*15+mp]);
        float e,o; upk(s,e,o);
        g_part[((size_t)blockIdx.y*30+2*mp)*1024   + nb + l2] = e;
        g_part[((size_t)blockIdx.y*30+2*mp+1)*1024 + nb + l2] = o;
    }
}

__global__ void k6b(const float* __restrict__ b){
    int idx = blockIdx.x*blockDim.x+threadIdx.x;
    if (idx >= 30*1024) return;
    int m = idx>>10, o = idx&1023;
    float s = b[o];
    #pragma unroll
    for (int q=0;q<K6_SPLIT;q++) s += g_part[((size_t)q*30+m)*1024+o];
    g_c1[idx] = (s >= 0.f) ? s : RRELU_S*s;
}

__global__ void k6c(const float* __restrict__ w, const float* __restrict__ b){
    int idx = blockIdx.x*blockDim.x+threadIdx.x;
    if (idx >= 30*256) return;
    int m = idx>>8, o = idx&255;
    const float* c1 = g_c1 + m*1024;
    float acc = b[o];
    #pragma unroll 4
    for (int k=0;k<1024;k++) acc = fmaf(c1[k], w[k*256+o], acc);
    g_c2[idx] = fmaxf(acc, 0.f);
}

__global__ void k6d(const float* __restrict__ w, const float* __restrict__ b){
    int idx = blockIdx.x*blockDim.x+threadIdx.x;
    if (idx >= 30*64) return;
    int m = idx>>6, o = idx&63;
    const float* c2 = g_c2 + m*256;
    float acc = b[o];
    #pragma unroll 4
    for (int k=0;k<256;k++) acc = fmaf(c2[k], w[k*64+o], acc);
    g_c3[idx] = fmaxf(acc, 0.f);
}

__global__ void k6e(const float* __restrict__ w, const float* __restrict__ b,
                    float* __restrict__ out){
    int m = threadIdx.x;
    if (m >= 30) return;
    float v[3];
    #pragma unroll
    for (int c=0;c<3;c++){
        float acc = b[c];
        #pragma unroll
        for (int k=0;k<64;k++) acc = fmaf(g_c3[m*64+k], w[k*3+c], acc);
        v[c]=acc;
    }
    float mx = fmaxf(v[0], fmaxf(v[1],v[2]));
    float lse = mx + logf(expf(v[0]-mx)+expf(v[1]-mx)+expf(v[2]-mx));
    #pragma unroll
    for (int c=0;c<3;c++) out[m*3+c] = v[c]-lse;
}

extern "C" void kernel_launch(void* const* d_in, const int* in_sizes, int n_in,
                              void* d_out, int out_size){
    const float* x      = (const float*)d_in[0];
    const float* c1w    = (const float*)d_in[1];
    const float* c1b    = (const float*)d_in[2];
    const float* bn1g   = (const float*)d_in[3];
    const float* bn1b   = (const float*)d_in[4];
    const float* c2w    = (const float*)d_in[5];
    const float* c2b    = (const float*)d_in[6];
    const float* bn2g   = (const float*)d_in[7];
    const float* bn2b   = (const float*)d_in[8];
    const float* c3w    = (const float*)d_in[9];
    const float* c3b    = (const float*)d_in[10];
    const float* bn3g   = (const float*)d_in[11];
    const float* bn3b   = (const float*)d_in[12];
    const float* few    = (const float*)d_in[13];
    const float* feb    = (const float*)d_in[14];
    const float* s1w    = (const float*)d_in[15];
    const float* s1b    = (const float*)d_in[16];
    const float* s2w    = (const float*)d_in[17];
    const float* s2b    = (const float*)d_in[18];
    const float* s3w    = (const float*)d_in[19];
    const float* s3b    = (const float*)d_in[20];
    const float* s4w    = (const float*)d_in[21];
    const float* s4b    = (const float*)d_in[22];
    const float* clw1   = (const float*)d_in[23];
    const float* clb1   = (const float*)d_in[24];
    const float* clw2   = (const float*)d_in[25];
    const float* clb2   = (const float*)d_in[26];
    const float* clw3   = (const float*)d_in[27];
    const float* clb3   = (const float*)d_in[28];
    const float* clw4   = (const float*)d_in[29];
    const float* clb4   = (const float*)d_in[30];
    float* out = (float*)d_out;

    static int smem_set = 0;
    if (!smem_set){
        cudaFuncSetAttribute(kconv, cudaFuncAttributeMaxDynamicSharedMemorySize, 49024);
        smem_set = 1;
    }

    kconv<<<NROWS, 256, 49024>>>(x, c1w, c1b, bn1g, bn1b,
                                 c2w, c2b, bn2g, bn2b,
                                 c3w, c3b, bn3g, bn3b);
    k4a<<<dim3(254, K4_SPLIT), 256>>>(few);
    k4b<<<(NROWS*32 + 255)/256, 256>>>(feb);
    k5<<<(NB*NPAIRS + 255)/256, 256>>>(s1w,s1b,s2w,s2b,s3w,s3b,s4w,s4b);
    k6a<<<dim3(32, K6_SPLIT), 256>>>(clw1);
    k6b<<<(30*1024 + 255)/256, 256>>>(clb1);
    k6c<<<(30*256 + 255)/256, 256>>>(clw2, clb2);
    k6d<<<(30*64 + 255)/256, 256>>>(clw3, clb3);
    k6e<<<1, 32>>>(clw4, clb4, out);
}

// round 5
// speedup vs baseline: 6.5055x; 1.0085x over previous
#include <cuda_runtime.h>
#include <math.h>

#define NB 30
#define NODES 135
#define NROWS (NB*NODES)     // 4050
#define NPAIRS 9045
#define TOTPAIR (NB*NPAIRS)  // 271350

#define BN_S 0.9999950001f   // 1/sqrt(1+1e-5)
#define RRELU_S 0.2291666667f

#define K4_SPLIT 9
#define K6_SPLIT 16

typedef unsigned long long u64;

// ---- packed fp32x2 helpers (Blackwell FFMA2 path) ----
__device__ __forceinline__ u64 pk(float lo, float hi){
    u64 r; asm("mov.b64 %0, {%1,%2};" : "=l"(r) : "f"(lo), "f"(hi)); return r;
}
__device__ __forceinline__ void upk(u64 v, float& lo, float& hi){
    asm("mov.b64 {%0,%1}, %2;" : "=f"(lo), "=f"(hi) : "l"(v));
}
__device__ __forceinline__ u64 fma2(u64 a, u64 b, u64 c){
    u64 d; asm("fma.rn.f32x2 %0, %1, %2, %3;" : "=l"(d) : "l"(a), "l"(b), "l"(c)); return d;
}
__device__ __forceinline__ u64 add2(u64 a, u64 b){
    u64 d; asm("add.rn.f32x2 %0, %1, %2;" : "=l"(d) : "l"(a), "l"(b)); return d;
}

// ---- scratch ----
__device__ float g_s3[NROWS*48*45];          // (4050, 2160)
__device__ float g_feats[NROWS*32];
__device__ float g_subj[NB*NPAIRS];
__device__ float g_p4[K4_SPLIT*NROWS*32];
__device__ float g_part[K6_SPLIT*NB*1024];
__device__ float g_c1[NB*1024];
__device__ float g_c2[NB*256];
__device__ float g_c3[NB*64];

__device__ __forceinline__ float leaky(float v){ return v > 0.f ? v : 0.01f*v; }

// ============================================================
// KCONV: fused conv1+conv2+conv3 per row. Dynamic smem 49024 B.
// stage2: 2 channel-pairs per task (x regs shared) -> FMA-bound
// stage3: 3 channel-pairs per task -> balanced, 240 tasks (1 pass)
// ============================================================
__global__ void kconv(const float* __restrict__ x,
                      const float* __restrict__ w1, const float* __restrict__ cb1,
                      const float* __restrict__ g1, const float* __restrict__ bb1,
                      const float* __restrict__ w2, const float* __restrict__ cb2,
                      const float* __restrict__ g2, const float* __restrict__ bb2,
                      const float* __restrict__ w3, const float* __restrict__ cb3,
                      const float* __restrict__ g3, const float* __restrict__ bb3){
    extern __shared__ float dsm[];
    float* s2s = dsm;                           // [0, 2944)
    float* s1s = dsm + 2944;                    // [2944, 5920)
    u64*   wp2 = (u64*)(dsm + 2944 + 2976);     // 1568 u64
    u64*   wp3 = (u64*)(dsm + 2944);            // 4656 u64 (phase B)

    __shared__ float xr[376];
    __shared__ float ws1[96], A1[32], B1[32], A2[64], B2[64];

    int n = blockIdx.x, tid = threadIdx.x;

    for (int i=tid;i<375;i+=256) xr[i] = x[n*375+i];
    if (tid < 96) ws1[tid] = w1[tid];
    if (tid < 32){ float a = g1[tid]*BN_S; A1[tid]=a; B1[tid]=fmaf(cb1[tid],a,bb1[tid]); }
    if (tid < 64){ float a = g2[tid]*BN_S; A2[tid]=a; B2[tid]=fmaf(cb2[tid],a,bb2[tid]); }
    for (int i=tid;i<1536;i+=256){
        int c = i/48, r = i%48;
        wp2[c*49+r] = pk(w2[(2*c)*48 + r], w2[(2*c+1)*48 + r]);
    }
    __syncthreads();

    // ---- stage 1: x(375) -> s1s(16,186) ----
    for (int t=tid;t<2976;t+=256){
        int c = t/186, l = t%186;
        float x0=xr[2*l], x1=xr[2*l+1], x2=xr[2*l+2], x3=xr[2*l+3];
        int c0=2*c, c1=2*c+1;
        float wa0=ws1[c0*3],wa1=ws1[c0*3+1],wa2=ws1[c0*3+2];
        float wb0=ws1[c1*3],wb1=ws1[c1*3+1],wb2=ws1[c1*3+2];
        float p00 = x0*wa0 + x1*wa1 + x2*wa2;
        float p01 = x1*wa0 + x2*wa1 + x3*wa2;
        float p10 = x0*wb0 + x1*wb1 + x2*wb2;
        float p11 = x1*wb0 + x2*wb1 + x3*wb2;
        float a0=A1[c0],b0=B1[c0],a1=A1[c1],b1=B1[c1];
        float v = fmaxf(fmaxf(leaky(fmaf(p00,a0,b0)), leaky(fmaf(p01,a0,b0))),
                        fmaxf(leaky(fmaf(p10,a1,b1)), leaky(fmaf(p11,a1,b1))));
        s1s[c*186+l] = v;
    }
    __syncthreads();

    // ---- stage 2: s1s(16,186) -> s2s(32,92). 16 cpg(2 pairs) x 23 l-tiles ----
    for (int t=tid;t<368;t+=256){
        int c2 = t & 15, lt = t >> 4;      // c2: 0..15, lt: 0..22
        int l0 = lt*4, px = 2*l0;
        u64 acA[8], acB[8];
        #pragma unroll
        for (int p=0;p<8;p++){ acA[p]=0ULL; acB[p]=0ULL; }
        const u64* wA = wp2 + c2*49;
        const u64* wB = wp2 + (c2+16)*49;
        for (int ci=0; ci<16; ci++){
            const float2* xp = (const float2*)(s1s + ci*186 + px);
            float xv[10];
            #pragma unroll
            for (int q=0;q<5;q++){ float2 v2 = xp[q]; xv[2*q]=v2.x; xv[2*q+1]=v2.y; }
            u64 xd[10];
            #pragma unroll
            for (int q=0;q<10;q++) xd[q] = pk(xv[q],xv[q]);
            u64 a0 = wA[ci*3], a1 = wA[ci*3+1], a2 = wA[ci*3+2];
            u64 b0 = wB[ci*3], b1 = wB[ci*3+1], b2 = wB[ci*3+2];
            #pragma unroll
            for (int p=0;p<8;p++){
                acA[p] = fma2(xd[p],a0, fma2(xd[p+1],a1, fma2(xd[p+2],a2, acA[p])));
                acB[p] = fma2(xd[p],b0, fma2(xd[p+1],b1, fma2(xd[p+2],b2, acB[p])));
            }
        }
        #pragma unroll
        for (int h=0;h<2;h++){
            int cp = c2 + 16*h;
            u64* ac = h ? acB : acA;
            float a0=A2[2*cp],b0=B2[2*cp],a1=A2[2*cp+1],b1=B2[2*cp+1];
            #pragma unroll
            for (int q=0;q<4;q++){
                float e0,o0,e1,o1;
                upk(ac[2*q], e0, o0);
                upk(ac[2*q+1], e1, o1);
                float v = fmaxf(fmaxf(leaky(fmaf(e0,a0,b0)), leaky(fmaf(e1,a0,b0))),
                                fmaxf(leaky(fmaf(o0,a1,b1)), leaky(fmaf(o1,a1,b1))));
                s2s[cp*92 + l0+q] = v;
            }
        }
    }
    __syncthreads();

    // ---- phase B weights ----
    for (int i=tid;i<4608;i+=256){
        int c = i/96, r = i%96;
        wp3[c*97+r] = pk(w3[(2*c)*96 + r], w3[(2*c+1)*96 + r]);
    }
    __syncthreads();

    // ---- stage 3: s2s(32,92) -> g_s3. 16 groups(3 pairs) x 15 l-tiles = 240 ----
    if (tid < 240){
        int g = tid & 15, lt = tid >> 4;   // g: 0..15, lt: 0..14
        int l0 = lt*3, px = 2*l0;
        u64 ac[3][6];
        #pragma unroll
        for (int h=0;h<3;h++)
            #pragma unroll
            for (int p=0;p<6;p++) ac[h][p]=0ULL;
        const u64* wA = wp3 + (3*g)*97;
        const u64* wB = wp3 + (3*g+1)*97;
        const u64* wC = wp3 + (3*g+2)*97;
        for (int ci=0; ci<32; ci++){
            const float2* xp = (const float2*)(s2s + ci*92 + px);
            float xv[8];
            #pragma unroll
            for (int q=0;q<4;q++){ float2 v2 = xp[q]; xv[2*q]=v2.x; xv[2*q+1]=v2.y; }
            u64 xd[8];
            #pragma unroll
            for (int q=0;q<8;q++) xd[q] = pk(xv[q],xv[q]);
            u64 a0 = wA[ci*3], a1 = wA[ci*3+1], a2 = wA[ci*3+2];
            u64 b0 = wB[ci*3], b1 = wB[ci*3+1], b2 = wB[ci*3+2];
            u64 c0 = wC[ci*3], c1 = wC[ci*3+1], c2 = wC[ci*3+2];
            #pragma unroll
            for (int p=0;p<6;p++){
                ac[0][p] = fma2(xd[p],a0, fma2(xd[p+1],a1, fma2(xd[p+2],a2, ac[0][p])));
                ac[1][p] = fma2(xd[p],b0, fma2(xd[p+1],b1, fma2(xd[p+2],b2, ac[1][p])));
                ac[2][p] = fma2(xd[p],c0, fma2(xd[p+1],c1, fma2(xd[p+2],c2, ac[2][p])));
            }
        }
        #pragma unroll
        for (int h=0;h<3;h++){
            int cp = 3*g + h;
            int c0=2*cp, c1=2*cp+1;
            float a0=__ldg(g3+c0)*BN_S, a1=__ldg(g3+c1)*BN_S;
            float b0=fmaf(__ldg(cb3+c0),a0,__ldg(bb3+c0));
            float b1=fmaf(__ldg(cb3+c1),a1,__ldg(bb3+c1));
            #pragma unroll
            for (int q=0;q<3;q++){
                float e0,o0,e1,o1;
                upk(ac[h][2*q], e0, o0);
                upk(ac[h][2*q+1], e1, o1);
                float v = fmaxf(fmaxf(leaky(fmaf(e0,a0,b0)), leaky(fmaf(e1,a0,b0))),
                                fmaxf(leaky(fmaf(o0,a1,b1)), leaky(fmaf(o1,a1,b1))));
                g_s3[(n*48+cp)*45 + l0+q] = v;
            }
        }
    }
}

// ============================================================
// K4a: split-K GEMM partials: s3(4050,2160) @ W(2160,32).
// ============================================================
__global__ void k4a(const float* __restrict__ w){
    __shared__ u64 ws2[48*16];
    int tid = threadIdx.x, o2 = tid & 15, r = tid >> 4;
    int n = blockIdx.x*16 + r;
    int nn = n < NROWS ? n : NROWS-1;
    int ks = blockIdx.y*240;
    u64 acc = 0ULL;
    for (int c0 = 0; c0 < 240; c0 += 48){
        __syncthreads();
        for (int i = tid; i < 384; i += 256){
            int kk = i >> 3, j = i & 7;
            float4 f = ((const float4*)(w + (ks + c0 + kk)*32))[j];
            ws2[kk*16 + 2*j]   = pk(f.x, f.y);
            ws2[kk*16 + 2*j+1] = pk(f.z, f.w);
        }
        const float4* hp = (const float4*)(g_s3 + (size_t)nn*2160 + ks + c0);
        float4 hv[12];
        #pragma unroll
        for (int q=0;q<12;q++) hv[q] = hp[q];
        __syncthreads();
        #pragma unroll
        for (int q=0;q<12;q++){
            acc = fma2(pk(hv[q].x,hv[q].x), ws2[(4*q+0)*16+o2], acc);
            acc = fma2(pk(hv[q].y,hv[q].y), ws2[(4*q+1)*16+o2], acc);
            acc = fma2(pk(hv[q].z,hv[q].z), ws2[(4*q+2)*16+o2], acc);
            acc = fma2(pk(hv[q].w,hv[q].w), ws2[(4*q+3)*16+o2], acc);
        }
    }
    if (n < NROWS){
        float e,o; upk(acc,e,o);
        *(float2*)(g_p4 + ((size_t)blockIdx.y*NROWS + n)*32 + 2*o2) = make_float2(e,o);
    }
}

__global__ void k4b(const float* __restrict__ b){
    int idx = blockIdx.x*blockDim.x + threadIdx.x;
    if (idx >= NROWS*32) return;
    int o = idx & 31;
    float s = b[o];
    #pragma unroll
    for (int q=0;q<K4_SPLIT;q++) s += g_p4[(size_t)q*NROWS*32 + idx];
    g_feats[idx] = s;
}

// ============================================================
// K5: sim MLP, 2 pairs per thread (weight LDS shared by 2 fma2).
// ============================================================
__device__ __forceinline__ void decode_pair(int pp, int& b, int& i, int& j){
    b = pp / NPAIRS;
    int p = pp - b*NPAIRS;
    int ii = (int)((269.0f - sqrtf(72361.0f - 8.0f*(float)p)) * 0.5f);
    if (ii < 0) ii = 0; if (ii > 133) ii = 133;
    while (ii > 0   && (ii*(269-ii))/2 > p) ii--;
    while (ii < 133 && ((ii+1)*(268-ii))/2 <= p) ii++;
    i = ii;
    j = ii + 1 + (p - (ii*(269-ii))/2);
}

__global__ void k5(const float* __restrict__ w1, const float* __restrict__ b1,
                   const float* __restrict__ w2, const float* __restrict__ b2,
                   const float* __restrict__ w3, const float* __restrict__ b3,
                   const float* __restrict__ w4, const float* __restrict__ b4){
    __shared__ u64 w1u[1024], w2u[256], w3u[64];
    __shared__ float w4s[8], b1s[32], b2s[16], b3s[8];
    __shared__ float b4s;
    int tid = threadIdx.x;
    for (int i=tid;i<1024;i+=256){ float2 v = *(const float2*)(w1+2*i); w1u[i]=pk(v.x,v.y); }
    if (tid<256){ float2 v = *(const float2*)(w2+2*tid); w2u[tid]=pk(v.x,v.y); }
    if (tid<64) { float2 v = *(const float2*)(w3+2*tid); w3u[tid]=pk(v.x,v.y); }
    if (tid<32)  b1s[tid]=b1[tid];
    if (tid<16)  b2s[tid]=b2[tid];
    if (tid<8)   { w4s[tid]=w4[tid]; b3s[tid]=b3[tid]; }
    if (tid==0)  b4s=b4[0];
    __syncthreads();
    int gid = blockIdx.x*blockDim.x + tid;
    int p0 = gid*2;
    if (p0 >= TOTPAIR) return;
    int p1 = p0 + 1;
    bool has1 = p1 < TOTPAIR;
    int pb1 = has1 ? p1 : p0;
    int b0i,i0,j0, b1i,i1,j1;
    decode_pair(p0, b0i, i0, j0);
    decode_pair(pb1, b1i, i1, j1);
    const float4* fi0 = (const float4*)(g_feats + (b0i*135+i0)*32);
    const float4* fj0 = (const float4*)(g_feats + (b0i*135+j0)*32);
    const float4* fi1 = (const float4*)(g_feats + (b1i*135+i1)*32);
    const float4* fj1 = (const float4*)(g_feats + (b1i*135+j1)*32);

    u64 A0[16], A1[16];
    #pragma unroll
    for (int o=0;o<16;o++){ u64 bb = pk(b1s[2*o], b1s[2*o+1]); A0[o]=bb; A1[o]=bb; }
    #pragma unroll
    for (int q=0;q<8;q++){
        float4 f0 = fi0[q], f1 = fi1[q];
        float fv0[4] = {f0.x,f0.y,f0.z,f0.w};
        float fv1[4] = {f1.x,f1.y,f1.z,f1.w};
        #pragma unroll
        for (int s=0;s<4;s++){
            u64 v0 = pk(fv0[s], fv0[s]);
            u64 v1 = pk(fv1[s], fv1[s]);
            int t = 4*q+s;
            #pragma unroll
            for (int o=0;o<16;o++){
                u64 ww = w1u[t*16+o];
                A0[o] = fma2(v0, ww, A0[o]);
                A1[o] = fma2(v1, ww, A1[o]);
            }
        }
    }
    #pragma unroll
    for (int q=0;q<8;q++){
        float4 f0 = fj0[q], f1 = fj1[q];
        float fv0[4] = {f0.x,f0.y,f0.z,f0.w};
        float fv1[4] = {f1.x,f1.y,f1.z,f1.w};
        #pragma unroll
        for (int s=0;s<4;s++){
            u64 v0 = pk(fv0[s], fv0[s]);
            u64 v1 = pk(fv1[s], fv1[s]);
            int t = 32 + 4*q+s;
            #pragma unroll
            for (int o=0;o<16;o++){
                u64 ww = w1u[t*16+o];
                A0[o] = fma2(v0, ww, A0[o]);
                A1[o] = fma2(v1, ww, A1[o]);
            }
        }
    }
    float h10[32], h11[32];
    #pragma unroll
    for (int o=0;o<16;o++){
        float e,od;
        upk(A0[o],e,od); h10[2*o]=fmaxf(e,0.f); h10[2*o+1]=fmaxf(od,0.f);
        upk(A1[o],e,od); h11[2*o]=fmaxf(e,0.f); h11[2*o+1]=fmaxf(od,0.f);
    }
    u64 B0[8], B1[8];
    #pragma unroll
    for (int o=0;o<8;o++){ u64 bb = pk(b2s[2*o], b2s[2*o+1]); B0[o]=bb; B1[o]=bb; }
    #pragma unroll
    for (int t=0;t<32;t++){
        u64 v0 = pk(h10[t], h10[t]);
        u64 v1 = pk(h11[t], h11[t]);
        #pragma unroll
        for (int o=0;o<8;o++){
            u64 ww = w2u[t*8+o];
            B0[o] = fma2(v0, ww, B0[o]);
            B1[o] = fma2(v1, ww, B1[o]);
        }
    }
    float h20[16], h21[16];
    #pragma unroll
    for (int o=0;o<8;o++){
        float e,od;
        upk(B0[o],e,od); h20[2*o]=fmaxf(e,0.f); h20[2*o+1]=fmaxf(od,0.f);
        upk(B1[o],e,od); h21[2*o]=fmaxf(e,0.f); h21[2*o+1]=fmaxf(od,0.f);
    }
    u64 C0[4], C1[4];
    #pragma unroll
    for (int o=0;o<4;o++){ u64 bb = pk(b3s[2*o], b3s[2*o+1]); C0[o]=bb; C1[o]=bb; }
    #pragma unroll
    for (int t=0;t<16;t++){
        u64 v0 = pk(h20[t], h20[t]);
        u64 v1 = pk(h21[t], h21[t]);
        #pragma unroll
        for (int o=0;o<4;o++){
            u64 ww = w3u[t*4+o];
            C0[o] = fma2(v0, ww, C0[o]);
            C1[o] = fma2(v1, ww, C1[o]);
        }
    }
    float o40 = b4s, o41 = b4s;
    #pragma unroll
    for (int o=0;o<4;o++){
        float e,od;
        upk(C0[o],e,od);
        o40 = fmaf(fmaxf(e,0.f),  w4s[2*o],   o40);
        o40 = fmaf(fmaxf(od,0.f), w4s[2*o+1], o40);
        upk(C1[o],e,od);
        o41 = fmaf(fmaxf(e,0.f),  w4s[2*o],   o41);
        o41 = fmaf(fmaxf(od,0.f), w4s[2*o+1], o41);
    }
    g_subj[p0] = tanhf(o40);
    if (has1) g_subj[p1] = tanhf(o41);
}

// ============================================================
// K6a: split-K GEMM partials: (30,9045)@(9045,1024).
// ============================================================
__global__ void k6a(const float* __restrict__ w){
    __shared__ __align__(16) char sbuf[33792];
    u64*   ssub2 = (u64*)sbuf;
    float* wt    = (float*)(sbuf + 17408);
    u64*   red   = (u64*)sbuf;
    int tid = threadIdx.x;
    int lane = tid & 31, kg = tid >> 5;
    int nb = blockIdx.x*32;
    int kstart = blockIdx.y*566;
    int kend = min(9045, kstart+566);
    u64 accp[15];
    #pragma unroll
    for (int m=0;m<15;m++) accp[m]=0ULL;
    for (int k0=kstart;k0<kend;k0+=128){
        int clen = min(128, kend-k0);
        __syncthreads();
        for (int i=tid;i<15*128;i+=256){
            int m = i>>7, kk = i&127;
            float v0=0.f, v1=0.f;
            if (kk<clen){
                v0 = g_subj[(2*m)*9045 + k0+kk];
                v1 = g_subj[(2*m+1)*9045 + k0+kk];
            }
            ssub2[kk*17+m] = pk(v0,v1);
        }
        for (int i=tid;i<1024;i+=256){
            int kk = i>>3, j = i&7;
            float4 f = make_float4(0.f,0.f,0.f,0.f);
            if (kk < clen)
                f = ((const float4*)(w + (size_t)(k0+kk)*1024 + nb))[j];
            ((float4*)(wt + kk*32))[j] = f;
        }
        __syncthreads();
        for (int kk=kg; kk<clen; kk+=8){
            float wv = wt[kk*32 + lane];
            u64 wv2 = pk(wv,wv);
            #pragma unroll
            for (int m=0;m<15;m++) accp[m] = fma2(ssub2[kk*17+m], wv2, accp[m]);
        }
    }
    __syncthreads();
    #pragma unroll
    for (int m=0;m<15;m++) red[tid*15+m] = accp[m];
    __syncthreads();
    for (int it=tid; it<32*15; it+=256){
        int l2 = it/15, mp = it%15;
        u64 s = red[l2*15+mp];
        #pragma unroll
        for (int q=1;q<8;q++) s = add2(s, red[(q*32+l2)*15+mp]);
        float e,o; upk(s,e,o);
        g_part[((size_t)blockIdx.y*30+2*mp)*1024   + nb + l2] = e;
        g_part[((size_t)blockIdx.y*30+2*mp+1)*1024 + nb + l2] = o;
    }
}

__global__ void k6b(const float* __restrict__ b){
    int idx = blockIdx.x*blockDim.x+threadIdx.x;
    if (idx >= 30*1024) return;
    int m = idx>>10, o = idx&1023;
    float s = b[o];
    #pragma unroll
    for (int q=0;q<K6_SPLIT;q++) s += g_part[((size_t)q*30+m)*1024+o];
    g_c1[idx] = (s >= 0.f) ? s : RRELU_S*s;
}

__global__ void k6c(const float* __restrict__ w, const float* __restrict__ b){
    int idx = blockIdx.x*blockDim.x+threadIdx.x;
    if (idx >= 30*256) return;
    int m = idx>>8, o = idx&255;
    const float* c1 = g_c1 + m*1024;
    float acc = b[o];
    #pragma unroll 4
    for (int k=0;k<1024;k++) acc = fmaf(c1[k], w[k*256+o], acc);
    g_c2[idx] = fmaxf(acc, 0.f);
}

__global__ void k6d(const float* __restrict__ w, const float* __restrict__ b){
    int idx = blockIdx.x*blockDim.x+threadIdx.x;
    if (idx >= 30*64) return;
    int m = idx>>6, o = idx&63;
    const float* c2 = g_c2 + m*256;
    float acc = b[o];
    #pragma unroll 4
    for (int k=0;k<256;k++) acc = fmaf(c2[k], w[k*64+o], acc);
    g_c3[idx] = fmaxf(acc, 0.f);
}

__global__ void k6e(const float* __restrict__ w, const float* __restrict__ b,
                    float* __restrict__ out){
    int m = threadIdx.x;
    if (m >= 30) return;
    float v[3];
    #pragma unroll
    for (int c=0;c<3;c++){
        float acc = b[c];
        #pragma unroll
        for (int k=0;k<64;k++) acc = fmaf(g_c3[m*64+k], w[k*3+c], acc);
        v[c]=acc;
    }
    float mx = fmaxf(v[0], fmaxf(v[1],v[2]));
    float lse = mx + logf(expf(v[0]-mx)+expf(v[1]-mx)+expf(v[2]-mx));
    #pragma unroll
    for (int c=0;c<3;c++) out[m*3+c] = v[c]-lse;
}

extern "C" void kernel_launch(void* const* d_in, const int* in_sizes, int n_in,
                              void* d_out, int out_size){
    const float* x      = (const float*)d_in[0];
    const float* c1w    = (const float*)d_in[1];
    const float* c1b    = (const float*)d_in[2];
    const float* bn1g   = (const float*)d_in[3];
    const float* bn1b   = (const float*)d_in[4];
    const float* c2w    = (const float*)d_in[5];
    const float* c2b    = (const float*)d_in[6];
    const float* bn2g   = (const float*)d_in[7];
    const float* bn2b   = (const float*)d_in[8];
    const float* c3w    = (const float*)d_in[9];
    const float* c3b    = (const float*)d_in[10];
    const float* bn3g   = (const float*)d_in[11];
    const float* bn3b   = (const float*)d_in[12];
    const float* few    = (const float*)d_in[13];
    const float* feb    = (const float*)d_in[14];
    const float* s1w    = (const float*)d_in[15];
    const float* s1b    = (const float*)d_in[16];
    const float* s2w    = (const float*)d_in[17];
    const float* s2b    = (const float*)d_in[18];
    const float* s3w    = (const float*)d_in[19];
    const float* s3b    = (const float*)d_in[20];
    const float* s4w    = (const float*)d_in[21];
    const float* s4b    = (const float*)d_in[22];
    const float* clw1   = (const float*)d_in[23];
    const float* clb1   = (const float*)d_in[24];
    const float* clw2   = (const float*)d_in[25];
    const float* clb2   = (const float*)d_in[26];
    const float* clw3   = (const float*)d_in[27];
    const float* clb3   = (const float*)d_in[28];
    const float* clw4   = (const float*)d_in[29];
    const float* clb4   = (const float*)d_in[30];
    float* out = (float*)d_out;

    static int smem_set = 0;
    if (!smem_set){
        cudaFuncSetAttribute(kconv, cudaFuncAttributeMaxDynamicSharedMemorySize, 49024);
        smem_set = 1;
    }

    kconv<<<NROWS, 256, 49024>>>(x, c1w, c1b, bn1g, bn1b,
                                 c2w, c2b, bn2g, bn2b,
                                 c3w, c3b, bn3g, bn3b);
    k4a<<<dim3(254, K4_SPLIT), 256>>>(few);
    k4b<<<(NROWS*32 + 255)/256, 256>>>(feb);
    k5<<<((TOTPAIR/2) + 255)/256, 256>>>(s1w,s1b,s2w,s2b,s3w,s3b,s4w,s4b);
    k6a<<<dim3(32, K6_SPLIT), 256>>>(clw1);
    k6b<<<(30*1024 + 255)/256, 256>>>(clb1);
    k6c<<<(30*256 + 255)/256, 256>>>(clw2, clb2);
    k6d<<<(30*64 + 255)/256, 256>>>(clw3, clb3);
    k6e<<<1, 32>>>(clw4, clb4, out);
}